// round 4
// baseline (speedup 1.0000x reference)
#include <cuda_runtime.h>
#include <cstdint>

#define BATCH 32
#define NFACT 64
#define DOBJ  128
#define GH    256
#define FOUT  32

// ---------------- scratch (no allocs allowed -> __device__ globals) ----------
__device__ float g_Ue[BATCH * NFACT * GH];       // x_i @ W_a + qc + b0
__device__ float g_Vv[BATCH * NFACT * GH];       // x_j @ W_b
__device__ float g_qc[BATCH * GH];               // q @ W_c + b0
__device__ float g_partial[BATCH * NFACT * GH];  // per-(b,j) partial embedding
__device__ float g_emb[BATCH * GH];

// ---------------- cp.async helpers ------------------------------------------
__device__ __forceinline__ void cp_async16(void* smem, const void* gmem) {
    uint32_t s = (uint32_t)__cvta_generic_to_shared(smem);
    asm volatile("cp.async.cg.shared.global [%0], [%1], 16;" :: "r"(s), "l"(gmem));
}
__device__ __forceinline__ void cp_commit() {
    asm volatile("cp.async.commit_group;" ::: "memory");
}

// ---------------- K1: qc[b][n] = q[b] @ W_c + b0 -----------------------------
__global__ void qc_kernel(const float* __restrict__ q,
                          const float* __restrict__ w0,
                          const float* __restrict__ b0) {
    int b = blockIdx.x, n = threadIdx.x;
    const float* qr = q + b * DOBJ;
    float acc = b0[n];
#pragma unroll 4
    for (int k = 0; k < DOBJ; k++)
        acc = fmaf(qr[k], w0[(2 * DOBJ + k) * GH + n], acc);
    g_qc[b * GH + n] = acc;
}

// ---------------- K2: Ue / Vv (64x256 = [64x128] @ [128x256]) ---------------
// grid: 64 blocks (b = blk>>1, part = blk&1). 256 threads as 8x32.
__global__ __launch_bounds__(256) void uv_kernel(const float* __restrict__ x,
                                                 const float* __restrict__ w0) {
    __shared__ float xs[NFACT * DOBJ];  // 32 KB
    int b = blockIdx.x >> 1, part = blockIdx.x & 1;
    const float4* xb = (const float4*)(x + b * NFACT * DOBJ);
    for (int v = threadIdx.x; v < NFACT * DOBJ / 4; v += 256)
        ((float4*)xs)[v] = xb[v];
    __syncthreads();

    int ty = threadIdx.x >> 5, tx = threadIdx.x & 31;
    const float* w = w0 + part * DOBJ * GH;  // rows [part*128, part*128+128)

    float acc[8][8];
#pragma unroll
    for (int r = 0; r < 8; r++)
#pragma unroll
        for (int c = 0; c < 8; c++) acc[r][c] = 0.f;

#pragma unroll 4
    for (int k = 0; k < DOBJ; k++) {
        float a[8], bf[8];
#pragma unroll
        for (int r = 0; r < 8; r++) a[r] = xs[(ty + 8 * r) * DOBJ + k];
#pragma unroll
        for (int c = 0; c < 8; c++) bf[c] = __ldg(&w[k * GH + tx + 32 * c]);
#pragma unroll
        for (int r = 0; r < 8; r++)
#pragma unroll
            for (int c = 0; c < 8; c++) acc[r][c] = fmaf(a[r], bf[c], acc[r][c]);
    }

    float* outp = (part == 0) ? g_Ue : g_Vv;
    const float* qc = g_qc + b * GH;
#pragma unroll
    for (int r = 0; r < 8; r++) {
        int row = ty + 8 * r;
#pragma unroll
        for (int c = 0; c < 8; c++) {
            int col = tx + 32 * c;
            float v = acc[r][c];
            if (part == 0) v += qc[col];
            outp[(b * NFACT + row) * GH + col] = v;
        }
    }
}

// ---------------- K3: the big fused kernel ----------------------------------
// One CTA per (b, j): h0 = relu(Ue[b,i]+Vv[b,j])  (64x256, SMEM)
//                     h1 = relu(h0 @ W1 + b1)     (64x256, SMEM)
//                     partial[b,j] = sum_i relu(h1 @ W2 + b2)
#define CHUNK (32 * GH)  // one K-chunk of W: 32 rows x 256 cols (floats)

// 64x256x256 GEMM core: A (SMEM, 64x256) @ Wg (GMEM 256x256) -> acc[8][8]
__device__ __forceinline__ void mm_64_256_256(const float* __restrict__ A,
                                              const float* __restrict__ Wg,
                                              float* wb, float acc[8][8]) {
    int ty = threadIdx.x >> 5, tx = threadIdx.x & 31;
#pragma unroll
    for (int r = 0; r < 8; r++)
#pragma unroll
        for (int c = 0; c < 8; c++) acc[r][c] = 0.f;

    // prologue: stage chunk 0
    {
#pragma unroll
        for (int i = 0; i < 8; i++) {
            int v = i * 256 + threadIdx.x;  // float4 index within chunk
            cp_async16(wb + v * 4, Wg + v * 4);
        }
        cp_commit();
    }

#pragma unroll 1
    for (int kt = 0; kt < 8; kt++) {
        if (kt < 7) {  // stage next chunk into the other buffer
            float* dst = wb + ((kt + 1) & 1) * CHUNK;
            const float* src = Wg + (kt + 1) * 32 * GH;
#pragma unroll
            for (int i = 0; i < 8; i++) {
                int v = i * 256 + threadIdx.x;
                cp_async16(dst + v * 4, src + v * 4);
            }
            cp_commit();
            asm volatile("cp.async.wait_group 1;" ::: "memory");
        } else {
            asm volatile("cp.async.wait_group 0;" ::: "memory");
        }
        __syncthreads();

        const float* wc = wb + (kt & 1) * CHUNK;
        const float* Ak = A + kt * 32;
#pragma unroll 4
        for (int k = 0; k < 32; k++) {
            float a[8], bf[8];
#pragma unroll
            for (int r = 0; r < 8; r++) a[r] = Ak[(ty + 8 * r) * GH + k];
#pragma unroll
            for (int c = 0; c < 8; c++) bf[c] = wc[k * GH + tx + 32 * c];
#pragma unroll
            for (int r = 0; r < 8; r++)
#pragma unroll
                for (int c = 0; c < 8; c++)
                    acc[r][c] = fmaf(a[r], bf[c], acc[r][c]);
        }
        __syncthreads();
    }
}

__global__ __launch_bounds__(256, 1) void rn_kernel(const float* __restrict__ w1,
                                                    const float* __restrict__ b1,
                                                    const float* __restrict__ w2,
                                                    const float* __restrict__ b2) {
    extern __shared__ float sm[];
    float* h0 = sm;                   // 64*256 floats
    float* h1 = sm + NFACT * GH;      // 64*256 floats
    float* wb = sm + 2 * NFACT * GH;  // 2 * CHUNK floats (double buffer)
    float* red = wb;                  // aliased reduction scratch (8x256)

    int b = blockIdx.x >> 6, j = blockIdx.x & 63;
    int ty = threadIdx.x >> 5, tx = threadIdx.x & 31;

    // ---- build h0 = relu(Ue[b,i,:] + Vv[b,j,:]) ----
    {
        const float4* Ue4 = (const float4*)(g_Ue + b * NFACT * GH);
        const float4* Vv4 = (const float4*)(g_Vv + (b * NFACT + j) * GH);
        for (int v = threadIdx.x; v < NFACT * GH / 4; v += 256) {
            float4 u = Ue4[v];
            float4 vv = Vv4[v & 63];
            float4 o;
            o.x = fmaxf(u.x + vv.x, 0.f);
            o.y = fmaxf(u.y + vv.y, 0.f);
            o.z = fmaxf(u.z + vv.z, 0.f);
            o.w = fmaxf(u.w + vv.w, 0.f);
            ((float4*)h0)[v] = o;
        }
    }
    __syncthreads();

    float acc[8][8];

    // ---- GEMM1: h1 = relu(h0 @ W1 + b1) ----
    mm_64_256_256(h0, w1, wb, acc);
#pragma unroll
    for (int c = 0; c < 8; c++) {
        int col = tx + 32 * c;
        float bias = __ldg(&b1[col]);
#pragma unroll
        for (int r = 0; r < 8; r++)
            h1[(ty + 8 * r) * GH + col] = fmaxf(acc[r][c] + bias, 0.f);
    }
    __syncthreads();

    // ---- GEMM2: partial = sum_rows relu(h1 @ W2 + b2) ----
    mm_64_256_256(h1, w2, wb, acc);
    float cs[8];
#pragma unroll
    for (int c = 0; c < 8; c++) {
        int col = tx + 32 * c;
        float bias = __ldg(&b2[col]);
        float s = 0.f;
#pragma unroll
        for (int r = 0; r < 8; r++) s += fmaxf(acc[r][c] + bias, 0.f);
        cs[c] = s;
    }
    // cross-warp column reduction (8 thread-rows -> 1)
#pragma unroll
    for (int c = 0; c < 8; c++) red[ty * GH + tx + 32 * c] = cs[c];
    __syncthreads();
    {
        int n = threadIdx.x;
        float s = 0.f;
#pragma unroll
        for (int t = 0; t < 8; t++) s += red[t * GH + n];
        g_partial[(b * NFACT + j) * GH + n] = s;
    }
}

// ---------------- K4: reduce partials over j --------------------------------
__global__ void reduce_kernel() {
    int b = blockIdx.x, n = threadIdx.x;
    float s = 0.f;
    const float* p = g_partial + b * NFACT * GH + n;
#pragma unroll 8
    for (int j = 0; j < NFACT; j++) s += p[j * GH];
    g_emb[b * GH + n] = s;
}

// ---------------- K5: f MLP -------------------------------------------------
__global__ void f_kernel(const float* __restrict__ fw0, const float* __restrict__ fb0,
                         const float* __restrict__ fw1, const float* __restrict__ fb1,
                         float* __restrict__ out) {
    __shared__ float e[GH];
    __shared__ float h[GH];
    int b = blockIdx.x, n = threadIdx.x;
    e[n] = g_emb[b * GH + n];
    __syncthreads();
    float acc = fb0[n];
#pragma unroll 4
    for (int k = 0; k < GH; k++) acc = fmaf(e[k], fw0[k * GH + n], acc);
    h[n] = fmaxf(acc, 0.f);
    __syncthreads();
    if (n < FOUT) {
        float a = fb1[n];
#pragma unroll 4
        for (int k = 0; k < GH; k++) a = fmaf(h[k], fw1[k * FOUT + n], a);
        out[b * FOUT + n] = a;
    }
}

// ---------------- launch ----------------------------------------------------
extern "C" void kernel_launch(void* const* d_in, const int* in_sizes, int n_in,
                              void* d_out, int out_size) {
    const float* x   = (const float*)d_in[0];
    const float* q   = (const float*)d_in[1];
    const float* gw0 = (const float*)d_in[2];
    const float* gb0 = (const float*)d_in[3];
    const float* gw1 = (const float*)d_in[4];
    const float* gb1 = (const float*)d_in[5];
    const float* gw2 = (const float*)d_in[6];
    const float* gb2 = (const float*)d_in[7];
    const float* fw0 = (const float*)d_in[8];
    const float* fb0 = (const float*)d_in[9];
    const float* fw1 = (const float*)d_in[10];
    const float* fb1 = (const float*)d_in[11];
    float* out = (float*)d_out;

    const int SMEM_B = (2 * NFACT * GH + 2 * CHUNK) * (int)sizeof(float);  // 196608 B
    cudaFuncSetAttribute(rn_kernel, cudaFuncAttributeMaxDynamicSharedMemorySize, SMEM_B);

    qc_kernel<<<BATCH, GH>>>(q, gw0, gb0);
    uv_kernel<<<BATCH * 2, 256>>>(x, gw0);
    rn_kernel<<<BATCH * NFACT, 256, SMEM_B>>>(gw1, gb1, gw2, gb2);
    reduce_kernel<<<BATCH, GH>>>();
    f_kernel<<<BATCH, GH>>>(fw0, fb0, fw1, fb1, out);
}

// round 6
// speedup vs baseline: 2.9826x; 2.9826x over previous
#include <cuda_runtime.h>
#include <cstdint>

#define BATCH 32
#define NFACT 64
#define DOBJ  128
#define GH    256
#define FOUT  32

// ---------------- scratch (__device__ globals; no allocs allowed) ------------
__device__ float g_Ue[BATCH * NFACT * GH];
__device__ float g_Vv[BATCH * NFACT * GH];
__device__ float g_qc[BATCH * GH];
__device__ float g_partial[BATCH * NFACT * GH];
__device__ float g_emb[BATCH * GH];
__device__ float g_W1c[GH * GH];  // tf32-rounded W1, [k][n]
__device__ float g_W2c[GH * GH];  // tf32-rounded W2, [k][n]

// ---------------- SMEM layout of rn_mma_kernel -------------------------------
#define AS_STRIDE 260                   // A rows padded: banks (4*gid+tig) unique
#define WS_STRIDE 264                   // W rows padded: banks (8*tig+gid) unique
#define OFF_B1 0
#define OFF_B2 1024
#define OFF_A  2048
#define A_BYTES (64 * AS_STRIDE * 4)    // 66560
#define OFF_W  (OFF_A + A_BYTES)        // 68608
#define WBUF_FLOATS (32 * WS_STRIDE)    // 8448
#define WBUF_B (WBUF_FLOATS * 4)        // 33792
#define SMEM_TOT (OFF_W + 2 * WBUF_B)   // 136192 B -> 1 CTA/SM

// ---------------- helpers ----------------------------------------------------
__device__ __forceinline__ uint32_t smem_u32(const void* p) {
    uint32_t a;
    asm("{ .reg .u64 t; cvta.to.shared.u64 t, %1; cvt.u32.u64 %0, t; }" : "=r"(a) : "l"(p));
    return a;
}
__device__ __forceinline__ void cp_async16(uint32_t s, const void* g) {
    asm volatile("cp.async.cg.shared.global [%0], [%1], 16;" :: "r"(s), "l"(g));
}
__device__ __forceinline__ void cp_commit() {
    asm volatile("cp.async.commit_group;" ::: "memory");
}
__device__ __forceinline__ float tf32r(float x) {
    uint32_t u;
    asm("cvt.rna.tf32.f32 %0, %1;" : "=r"(u) : "f"(x));
    return __uint_as_float(u);
}
__device__ __forceinline__ void mma8(float c[4], const uint32_t a[4], const uint32_t b[2]) {
    asm volatile(
        "mma.sync.aligned.m16n8k8.row.col.f32.tf32.tf32.f32 "
        "{%0,%1,%2,%3}, {%4,%5,%6,%7}, {%8,%9}, {%0,%1,%2,%3};"
        : "+f"(c[0]), "+f"(c[1]), "+f"(c[2]), "+f"(c[3])
        : "r"(a[0]), "r"(a[1]), "r"(a[2]), "r"(a[3]), "r"(b[0]), "r"(b[1]));
}

// ---------------- K1: qc = q @ W_c + b0 --------------------------------------
__global__ void qc_kernel(const float* __restrict__ q, const float* __restrict__ w0,
                          const float* __restrict__ b0) {
    int b = blockIdx.x, n = threadIdx.x;
    const float* qr = q + b * DOBJ;
    float acc = b0[n];
#pragma unroll 4
    for (int k = 0; k < DOBJ; k++) acc = fmaf(qr[k], w0[(2 * DOBJ + k) * GH + n], acc);
    g_qc[b * GH + n] = acc;
}

// ---------------- K2: Ue / Vv ------------------------------------------------
__global__ __launch_bounds__(256) void uv_kernel(const float* __restrict__ x,
                                                 const float* __restrict__ w0) {
    __shared__ float xs[NFACT * DOBJ];
    int b = blockIdx.x >> 1, part = blockIdx.x & 1;
    const float4* xb = (const float4*)(x + b * NFACT * DOBJ);
    for (int v = threadIdx.x; v < NFACT * DOBJ / 4; v += 256) ((float4*)xs)[v] = xb[v];
    __syncthreads();

    int ty = threadIdx.x >> 5, tx = threadIdx.x & 31;
    const float* w = w0 + part * DOBJ * GH;
    float acc[8][8];
#pragma unroll
    for (int r = 0; r < 8; r++)
#pragma unroll
        for (int c = 0; c < 8; c++) acc[r][c] = 0.f;
#pragma unroll 4
    for (int k = 0; k < DOBJ; k++) {
        float a[8], bf[8];
#pragma unroll
        for (int r = 0; r < 8; r++) a[r] = xs[(ty + 8 * r) * DOBJ + k];
#pragma unroll
        for (int c = 0; c < 8; c++) bf[c] = __ldg(&w[k * GH + tx + 32 * c]);
#pragma unroll
        for (int r = 0; r < 8; r++)
#pragma unroll
            for (int c = 0; c < 8; c++) acc[r][c] = fmaf(a[r], bf[c], acc[r][c]);
    }
    float* outp = (part == 0) ? g_Ue : g_Vv;
    const float* qc = g_qc + b * GH;
#pragma unroll
    for (int r = 0; r < 8; r++)
#pragma unroll
        for (int c = 0; c < 8; c++) {
            float v = acc[r][c];
            if (part == 0) v += qc[tx + 32 * c];
            outp[(b * NFACT + ty + 8 * r) * GH + tx + 32 * c] = v;
        }
}

// ---------------- K2b: tf32 pre-round of W (RNA; lossless under HW trunc) ----
__global__ void cvt_kernel(const float* __restrict__ in, float* __restrict__ out) {
    int i = blockIdx.x * 256 + threadIdx.x;
    out[i] = tf32r(in[i]);
}

// ---------------- K3: mma.sync tf32 fused kernel -----------------------------
__device__ __forceinline__ void load_w_chunk(uint32_t su, const float* __restrict__ W,
                                             int kc, int buf) {
    const float4* src = (const float4*)(W + kc * 32 * GH);
    uint32_t dst = su + OFF_W + buf * WBUF_B;
#pragma unroll
    for (int i = 0; i < 8; i++) {
        int p = threadIdx.x + i * 256;  // 0..2047 float4 slots (32 rows x 64)
        int row = p >> 6, c4 = p & 63;
        cp_async16(dst + (row * WS_STRIDE + c4 * 4) * 4, src + row * 64 + c4);
    }
    cp_commit();
}

// one 64x256x256 tf32 GEMM: A (SMEM, rows x AS_STRIDE) x W (streamed) -> c regs
__device__ __forceinline__ void gemm_mma(uint32_t su, const uint32_t* __restrict__ Au,
                                         const uint32_t* __restrict__ Wu,
                                         const float* __restrict__ Wg,
                                         int m0, int n0, int gid, int tig,
                                         float c[2][8][4]) {
#pragma unroll 1
    for (int kc = 0; kc < 8; kc++) {
        if (kc < 7) asm volatile("cp.async.wait_group 1;" ::: "memory");
        else        asm volatile("cp.async.wait_group 0;" ::: "memory");
        __syncthreads();
        const uint32_t* Ws = Wu + (kc & 1) * WBUF_FLOATS;
#pragma unroll
        for (int ks = 0; ks < 4; ks++) {
            int kg = kc * 32 + ks * 8;
            uint32_t a[2][4];
#pragma unroll
            for (int mt = 0; mt < 2; mt++) {
                const uint32_t* ap = Au + (m0 + mt * 16 + gid) * AS_STRIDE + kg + tig;
                a[mt][0] = ap[0];
                a[mt][1] = ap[8 * AS_STRIDE];
                a[mt][2] = ap[4];
                a[mt][3] = ap[8 * AS_STRIDE + 4];
            }
#pragma unroll
            for (int nt = 0; nt < 8; nt++) {
                const uint32_t* bp = Ws + (ks * 8 + tig) * WS_STRIDE + n0 + nt * 8 + gid;
                uint32_t bfr[2] = {bp[0], bp[4 * WS_STRIDE]};
                mma8(c[0][nt], a[0], bfr);
                mma8(c[1][nt], a[1], bfr);
            }
        }
        __syncthreads();
        if (kc < 6) load_w_chunk(su, Wg, kc + 2, kc & 1);
    }
}

__global__ __launch_bounds__(256, 1) void rn_mma_kernel(const float* __restrict__ b1g,
                                                        const float* __restrict__ b2g) {
    extern __shared__ char smc[];
    uint32_t su = smem_u32(smc);
    float* As = (float*)(smc + OFF_A);
    const uint32_t* Au = (const uint32_t*)As;
    const uint32_t* Wu = (const uint32_t*)(smc + OFF_W);
    float* b1s = (float*)(smc + OFF_B1);
    float* b2s = (float*)(smc + OFF_B2);

    int tid = threadIdx.x, lane = tid & 31, wid = tid >> 5;
    int gid = lane >> 2, tig = lane & 3;
    int m0 = (wid & 1) * 32, n0 = (wid >> 1) * 64;
    int b = blockIdx.x >> 6, j = blockIdx.x & 63;

    b1s[tid] = b1g[tid];
    b2s[tid] = b2g[tid];

    // prefetch W1 chunks 0,1 (independent of h0 build)
    load_w_chunk(su, g_W1c, 0, 0);
    load_w_chunk(su, g_W1c, 1, 1);

    // ---- build h0 = tf32(relu(Ue[b,i] + Vv[b,j])) into A ----
    {
        const float4* UeB = (const float4*)(g_Ue + b * NFACT * GH);
        const float4* VvB = (const float4*)(g_Vv + (b * NFACT + j) * GH);
#pragma unroll
        for (int it = 0; it < 16; it++) {
            int p = tid + it * 256;  // 4096 float4 slots: 64 rows x 64
            int i = p >> 6, c4 = p & 63;
            float4 u = UeB[i * 64 + c4];
            float4 v = VvB[c4];
            float4 o;
            o.x = tf32r(fmaxf(u.x + v.x, 0.f));
            o.y = tf32r(fmaxf(u.y + v.y, 0.f));
            o.z = tf32r(fmaxf(u.z + v.z, 0.f));
            o.w = tf32r(fmaxf(u.w + v.w, 0.f));
            *(float4*)(As + i * AS_STRIDE + c4 * 4) = o;
        }
    }
    __syncthreads();

    float c[2][8][4];
#pragma unroll
    for (int mt = 0; mt < 2; mt++)
#pragma unroll
        for (int nt = 0; nt < 8; nt++)
#pragma unroll
            for (int q = 0; q < 4; q++) c[mt][nt][q] = 0.f;

    // ---- GEMM1: D1 = h0 @ W1 ----
    gemm_mma(su, Au, Wu, g_W1c, m0, n0, gid, tig, c);

    // prefetch W2 chunks 0,1 (W buffers free after GEMM1's final sync)
    load_w_chunk(su, g_W2c, 0, 0);
    load_w_chunk(su, g_W2c, 1, 1);

    // ---- epilogue1: h1 = tf32(relu(D1 + b1)) -> A (aliased) ----
#pragma unroll
    for (int mt = 0; mt < 2; mt++)
#pragma unroll
        for (int nt = 0; nt < 8; nt++) {
            int r = m0 + mt * 16 + gid, col = n0 + nt * 8 + 2 * tig;
            float bb0 = b1s[col], bb1 = b1s[col + 1];
            As[r * AS_STRIDE + col]           = tf32r(fmaxf(c[mt][nt][0] + bb0, 0.f));
            As[r * AS_STRIDE + col + 1]       = tf32r(fmaxf(c[mt][nt][1] + bb1, 0.f));
            As[(r + 8) * AS_STRIDE + col]     = tf32r(fmaxf(c[mt][nt][2] + bb0, 0.f));
            As[(r + 8) * AS_STRIDE + col + 1] = tf32r(fmaxf(c[mt][nt][3] + bb1, 0.f));
            c[mt][nt][0] = c[mt][nt][1] = c[mt][nt][2] = c[mt][nt][3] = 0.f;
        }
    __syncthreads();

    // ---- GEMM2: D2 = h1 @ W2 ----
    gemm_mma(su, Au, Wu, g_W2c, m0, n0, gid, tig, c);

    // ---- epilogue2: relu(D2 + b2) staged into A (free now), column sums ----
#pragma unroll
    for (int mt = 0; mt < 2; mt++)
#pragma unroll
        for (int nt = 0; nt < 8; nt++) {
            int r = m0 + mt * 16 + gid, col = n0 + nt * 8 + 2 * tig;
            float bb0 = b2s[col], bb1 = b2s[col + 1];
            As[r * AS_STRIDE + col]           = fmaxf(c[mt][nt][0] + bb0, 0.f);
            As[r * AS_STRIDE + col + 1]       = fmaxf(c[mt][nt][1] + bb1, 0.f);
            As[(r + 8) * AS_STRIDE + col]     = fmaxf(c[mt][nt][2] + bb0, 0.f);
            As[(r + 8) * AS_STRIDE + col + 1] = fmaxf(c[mt][nt][3] + bb1, 0.f);
        }
    __syncthreads();
    {
        int n = tid;  // 0..255 columns
        float s = 0.f;
#pragma unroll 8
        for (int i = 0; i < 64; i++) s += As[i * AS_STRIDE + n];
        g_partial[(b * NFACT + j) * GH + n] = s;
    }
}

// ---------------- K4: reduce over j ------------------------------------------
__global__ void reduce_kernel() {
    int b = blockIdx.x, n = threadIdx.x;
    float s = 0.f;
    const float* p = g_partial + b * NFACT * GH + n;
#pragma unroll 8
    for (int j = 0; j < NFACT; j++) s += p[j * GH];
    g_emb[b * GH + n] = s;
}

// ---------------- K5: f MLP --------------------------------------------------
__global__ void f_kernel(const float* __restrict__ fw0, const float* __restrict__ fb0,
                         const float* __restrict__ fw1, const float* __restrict__ fb1,
                         float* __restrict__ out) {
    __shared__ float e[GH];
    __shared__ float h[GH];
    int b = blockIdx.x, n = threadIdx.x;
    e[n] = g_emb[b * GH + n];
    __syncthreads();
    float acc = fb0[n];
#pragma unroll 4
    for (int k = 0; k < GH; k++) acc = fmaf(e[k], fw0[k * GH + n], acc);
    h[n] = fmaxf(acc, 0.f);
    __syncthreads();
    if (n < FOUT) {
        float a = fb1[n];
#pragma unroll 4
        for (int k = 0; k < GH; k++) a = fmaf(h[k], fw1[k * FOUT + n], a);
        out[b * FOUT + n] = a;
    }
}

// ---------------- launch ----------------------------------------------------
extern "C" void kernel_launch(void* const* d_in, const int* in_sizes, int n_in,
                              void* d_out, int out_size) {
    const float* x   = (const float*)d_in[0];
    const float* q   = (const float*)d_in[1];
    const float* gw0 = (const float*)d_in[2];
    const float* gb0 = (const float*)d_in[3];
    const float* gw1 = (const float*)d_in[4];
    const float* gb1 = (const float*)d_in[5];
    const float* gw2 = (const float*)d_in[6];
    const float* gb2 = (const float*)d_in[7];
    const float* fw0 = (const float*)d_in[8];
    const float* fb0 = (const float*)d_in[9];
    const float* fw1 = (const float*)d_in[10];
    const float* fb1 = (const float*)d_in[11];
    float* out = (float*)d_out;

    cudaFuncSetAttribute(rn_mma_kernel, cudaFuncAttributeMaxDynamicSharedMemorySize, SMEM_TOT);

    float *w1c = nullptr, *w2c = nullptr;
    cudaGetSymbolAddress((void**)&w1c, g_W1c);
    cudaGetSymbolAddress((void**)&w2c, g_W2c);

    qc_kernel<<<BATCH, GH>>>(q, gw0, gb0);
    uv_kernel<<<BATCH * 2, 256>>>(x, gw0);
    cvt_kernel<<<GH * GH / 256, 256>>>(gw1, w1c);
    cvt_kernel<<<GH * GH / 256, 256>>>(gw2, w2c);
    rn_mma_kernel<<<BATCH * NFACT, 256, SMEM_TOT>>>(gb1, gb2);
    reduce_kernel<<<BATCH, GH>>>();
    f_kernel<<<BATCH, GH>>>(fw0, fb0, fw1, fb1, out);
}

// round 7
// speedup vs baseline: 4.6669x; 1.5647x over previous
#include <cuda_runtime.h>
#include <cuda_fp16.h>
#include <cstdint>

#define BATCH 32
#define NFACT 64
#define DOBJ  128
#define GH    256
#define FOUT  32

// ---------------- scratch (__device__ globals; no allocs allowed) ------------
__device__ float  g_Ue[BATCH * NFACT * GH];
__device__ float  g_Vv[BATCH * NFACT * GH];
__device__ float  g_partial[BATCH * NFACT * GH];
__device__ __half g_W1h[GH * GH];  // [n][k] = half(W1[k][n])
__device__ __half g_W2h[GH * GH];  // [n][k] = half(W2[k][n])

// ---------------- SMEM layout of rn_mma_kernel (halves) ----------------------
#define AS_STRIDE_H 264                  // A row stride in halves (132 words)
#define WS_STRIDE_H 40                   // W row stride in halves (20 words)
#define OFF_B1 0
#define OFF_B2 1024
#define OFF_A  2048
#define A_BYTES (64 * AS_STRIDE_H * 2)   // 33792
#define OFF_W  (OFF_A + A_BYTES)         // 35840
#define WBUF_WORDS (GH * WS_STRIDE_H / 2)  // 2560 words per buffer
#define WBUF_B (GH * WS_STRIDE_H * 2)    // 20480 B
#define SMEM_TOT (OFF_W + 2 * WBUF_B)    // 76800 B -> 2 CTAs/SM
#define STG_STRIDE 260                   // epilogue-2 float staging stride

// ---------------- helpers ----------------------------------------------------
__device__ __forceinline__ uint32_t smem_u32(const void* p) {
    uint32_t a;
    asm("{ .reg .u64 t; cvta.to.shared.u64 t, %1; cvt.u32.u64 %0, t; }" : "=r"(a) : "l"(p));
    return a;
}
__device__ __forceinline__ void cp_async16(uint32_t s, const void* g) {
    asm volatile("cp.async.cg.shared.global [%0], [%1], 16;" :: "r"(s), "l"(g));
}
__device__ __forceinline__ void cp_commit() {
    asm volatile("cp.async.commit_group;" ::: "memory");
}
__device__ __forceinline__ void mma16(float c[4], const uint32_t a[4], const uint32_t b[2]) {
    asm volatile(
        "mma.sync.aligned.m16n8k16.row.col.f32.f16.f16.f32 "
        "{%0,%1,%2,%3}, {%4,%5,%6,%7}, {%8,%9}, {%0,%1,%2,%3};"
        : "+f"(c[0]), "+f"(c[1]), "+f"(c[2]), "+f"(c[3])
        : "r"(a[0]), "r"(a[1]), "r"(a[2]), "r"(a[3]), "r"(b[0]), "r"(b[1]));
}
__device__ __forceinline__ uint32_t pack_h2(float lo, float hi) {
    __half2 h = __floats2half2_rn(lo, hi);
    return *(uint32_t*)&h;
}

// ---------------- K1: Ue / Vv (qc fused in) ----------------------------------
__global__ __launch_bounds__(256) void uv_kernel(const float* __restrict__ x,
                                                 const float* __restrict__ q,
                                                 const float* __restrict__ w0,
                                                 const float* __restrict__ b0) {
    __shared__ float xs[NFACT * DOBJ];   // 32 KB
    __shared__ float qcs[GH];
    int b = blockIdx.x >> 1, part = blockIdx.x & 1;
    const float4* xb = (const float4*)(x + b * NFACT * DOBJ);
    for (int v = threadIdx.x; v < NFACT * DOBJ / 4; v += 256) ((float4*)xs)[v] = xb[v];
    if (part == 0) {  // qc[col] = b0[col] + q[b] . W0[256+k][col]
        int col = threadIdx.x;
        const float* qr = q + b * DOBJ;
        float acc = b0[col];
#pragma unroll 4
        for (int k = 0; k < DOBJ; k++)
            acc = fmaf(qr[k], w0[(2 * DOBJ + k) * GH + col], acc);
        qcs[col] = acc;
    }
    __syncthreads();

    int ty = threadIdx.x >> 5, tx = threadIdx.x & 31;
    const float* w = w0 + part * DOBJ * GH;
    float acc[8][8];
#pragma unroll
    for (int r = 0; r < 8; r++)
#pragma unroll
        for (int c = 0; c < 8; c++) acc[r][c] = 0.f;
#pragma unroll 4
    for (int k = 0; k < DOBJ; k++) {
        float a[8], bf[8];
#pragma unroll
        for (int r = 0; r < 8; r++) a[r] = xs[(ty + 8 * r) * DOBJ + k];
#pragma unroll
        for (int c = 0; c < 8; c++) bf[c] = __ldg(&w[k * GH + tx + 32 * c]);
#pragma unroll
        for (int r = 0; r < 8; r++)
#pragma unroll
            for (int c = 0; c < 8; c++) acc[r][c] = fmaf(a[r], bf[c], acc[r][c]);
    }
    float* outp = (part == 0) ? g_Ue : g_Vv;
#pragma unroll
    for (int r = 0; r < 8; r++)
#pragma unroll
        for (int c = 0; c < 8; c++) {
            float v = acc[r][c];
            if (part == 0) v += qcs[tx + 32 * c];
            outp[(b * NFACT + ty + 8 * r) * GH + tx + 32 * c] = v;
        }
}

// ---------------- K2: W1/W2 -> transposed half [n][k] -------------------------
__global__ void w_half_kernel(const float* __restrict__ w1, const float* __restrict__ w2) {
    __shared__ float tile[32][33];
    const float* in = blockIdx.z ? w2 : w1;
    __half* out = blockIdx.z ? g_W2h : g_W1h;
    int bx = blockIdx.x * 32, by = blockIdx.y * 32;  // bx: n, by: k
#pragma unroll
    for (int dy = 0; dy < 32; dy += 8)
        tile[threadIdx.y + dy][threadIdx.x] = in[(by + threadIdx.y + dy) * GH + bx + threadIdx.x];
    __syncthreads();
#pragma unroll
    for (int dy = 0; dy < 32; dy += 8)
        out[(bx + threadIdx.y + dy) * GH + by + threadIdx.x] =
            __float2half_rn(tile[threadIdx.x][threadIdx.y + dy]);
}

// ---------------- K3: fp16 mma.sync fused kernel -----------------------------
// W chunk kc: halves [kc*32, kc*32+32) of every n-row of Wh[n][k]
__device__ __forceinline__ void load_w_chunk(uint32_t su, const __half* __restrict__ Wh,
                                             int kc, int buf) {
    const __half* src = Wh + kc * 32;
    uint32_t dst = su + OFF_W + buf * WBUF_B;
#pragma unroll
    for (int i = 0; i < 4; i++) {
        int p = threadIdx.x + i * 256;  // 1024 slots: 256 n-rows x 4 x 16B
        int n = p >> 2, c4 = p & 3;
        cp_async16(dst + n * (WS_STRIDE_H * 2) + c4 * 16, src + n * GH + c4 * 8);
    }
    cp_commit();
}

// one 64x256x256 fp16 GEMM: A (SMEM halves) x Wh (streamed) -> c regs (f32)
__device__ __forceinline__ void gemm_mma(uint32_t su, const uint32_t* __restrict__ Au,
                                         const uint32_t* __restrict__ Wu,
                                         const __half* __restrict__ Wh,
                                         int m0, int n0, int gid, int tig,
                                         float c[2][8][4]) {
#pragma unroll 1
    for (int kc = 0; kc < 8; kc++) {
        if (kc < 7) asm volatile("cp.async.wait_group 1;" ::: "memory");
        else        asm volatile("cp.async.wait_group 0;" ::: "memory");
        __syncthreads();
        const uint32_t* Ws = Wu + (kc & 1) * WBUF_WORDS;
#pragma unroll
        for (int ks = 0; ks < 2; ks++) {  // two k16 steps per 32-k chunk
            uint32_t a[2][4];
#pragma unroll
            for (int mt = 0; mt < 2; mt++) {
                const uint32_t* ap =
                    Au + (m0 + mt * 16 + gid) * (AS_STRIDE_H / 2) + kc * 16 + ks * 8 + tig;
                a[mt][0] = ap[0];
                a[mt][1] = ap[8 * (AS_STRIDE_H / 2)];
                a[mt][2] = ap[4];
                a[mt][3] = ap[8 * (AS_STRIDE_H / 2) + 4];
            }
#pragma unroll
            for (int nt = 0; nt < 8; nt++) {
                const uint32_t* bp =
                    Ws + (n0 + nt * 8 + gid) * (WS_STRIDE_H / 2) + ks * 8 + tig;
                uint32_t bfr[2] = {bp[0], bp[4]};
                mma16(c[0][nt], a[0], bfr);
                mma16(c[1][nt], a[1], bfr);
            }
        }
        __syncthreads();
        if (kc < 6) load_w_chunk(su, Wh, kc + 2, kc & 1);
    }
}

__global__ __launch_bounds__(256, 2) void rn_mma_kernel(const float* __restrict__ b1g,
                                                        const float* __restrict__ b2g) {
    extern __shared__ char smc[];
    uint32_t su = smem_u32(smc);
    __half* As = (__half*)(smc + OFF_A);
    const uint32_t* Au = (const uint32_t*)As;
    const uint32_t* Wu = (const uint32_t*)(smc + OFF_W);
    float* b1s = (float*)(smc + OFF_B1);
    float* b2s = (float*)(smc + OFF_B2);

    int tid = threadIdx.x, lane = tid & 31, wid = tid >> 5;
    int gid = lane >> 2, tig = lane & 3;
    int m0 = (wid & 1) * 32, n0 = (wid >> 1) * 64;
    int b = blockIdx.x >> 6, j = blockIdx.x & 63;

    b1s[tid] = b1g[tid];
    b2s[tid] = b2g[tid];

    // prefetch W1 chunks 0,1 (independent of h0 build)
    load_w_chunk(su, g_W1h, 0, 0);
    load_w_chunk(su, g_W1h, 1, 1);

    // ---- build h0 = half(relu(Ue[b,i] + Vv[b,j])) into A ----
    {
        const float4* UeB = (const float4*)(g_Ue + b * NFACT * GH);
        const float4* VvB = (const float4*)(g_Vv + (b * NFACT + j) * GH);
#pragma unroll
        for (int it = 0; it < 16; it++) {
            int p = tid + it * 256;  // 4096 slots: 64 rows x 64 float4-groups
            int i = p >> 6, c4 = p & 63;
            float4 u = UeB[i * 64 + c4];
            float4 v = VvB[c4];
            uint2 o;
            o.x = pack_h2(fmaxf(u.x + v.x, 0.f), fmaxf(u.y + v.y, 0.f));
            o.y = pack_h2(fmaxf(u.z + v.z, 0.f), fmaxf(u.w + v.w, 0.f));
            *(uint2*)((char*)smc + OFF_A + i * (AS_STRIDE_H * 2) + c4 * 8) = o;
        }
    }
    __syncthreads();

    float c[2][8][4];
#pragma unroll
    for (int mt = 0; mt < 2; mt++)
#pragma unroll
        for (int nt = 0; nt < 8; nt++)
#pragma unroll
            for (int q = 0; q < 4; q++) c[mt][nt][q] = 0.f;

    // ---- GEMM1: D1 = h0 @ W1 ----
    gemm_mma(su, Au, Wu, g_W1h, m0, n0, gid, tig, c);

    // prefetch W2 chunks 0,1 (buffers free after GEMM1's trailing sync)
    load_w_chunk(su, g_W2h, 0, 0);
    load_w_chunk(su, g_W2h, 1, 1);

    // ---- epilogue1: h1 = half(relu(D1 + b1)) -> A (aliased) ----
#pragma unroll
    for (int mt = 0; mt < 2; mt++)
#pragma unroll
        for (int nt = 0; nt < 8; nt++) {
            int r = m0 + mt * 16 + gid, col = n0 + nt * 8 + 2 * tig;
            float bb0 = b1s[col], bb1 = b1s[col + 1];
            *(uint32_t*)(As + r * AS_STRIDE_H + col) =
                pack_h2(fmaxf(c[mt][nt][0] + bb0, 0.f), fmaxf(c[mt][nt][1] + bb1, 0.f));
            *(uint32_t*)(As + (r + 8) * AS_STRIDE_H + col) =
                pack_h2(fmaxf(c[mt][nt][2] + bb0, 0.f), fmaxf(c[mt][nt][3] + bb1, 0.f));
            c[mt][nt][0] = c[mt][nt][1] = c[mt][nt][2] = c[mt][nt][3] = 0.f;
        }
    __syncthreads();

    // ---- GEMM2: D2 = h1 @ W2 ----
    gemm_mma(su, Au, Wu, g_W2h, m0, n0, gid, tig, c);

    // ---- epilogue2: relu(D2 + b2) staged (A+W regions free), column sums ----
    {
        float* stg = (float*)(smc + OFF_A);  // 64 x STG_STRIDE floats
#pragma unroll
        for (int mt = 0; mt < 2; mt++)
#pragma unroll
            for (int nt = 0; nt < 8; nt++) {
                int r = m0 + mt * 16 + gid, col = n0 + nt * 8 + 2 * tig;
                float bb0 = b2s[col], bb1 = b2s[col + 1];
                stg[r * STG_STRIDE + col]           = fmaxf(c[mt][nt][0] + bb0, 0.f);
                stg[r * STG_STRIDE + col + 1]       = fmaxf(c[mt][nt][1] + bb1, 0.f);
                stg[(r + 8) * STG_STRIDE + col]     = fmaxf(c[mt][nt][2] + bb0, 0.f);
                stg[(r + 8) * STG_STRIDE + col + 1] = fmaxf(c[mt][nt][3] + bb1, 0.f);
            }
        __syncthreads();
        int n = tid;
        float s = 0.f;
#pragma unroll 8
        for (int i = 0; i < 64; i++) s += stg[i * STG_STRIDE + n];
        g_partial[(b * NFACT + j) * GH + n] = s;
    }
}

// ---------------- K4: f MLP (reduce over j fused in) -------------------------
__global__ void f_kernel(const float* __restrict__ fw0, const float* __restrict__ fb0,
                         const float* __restrict__ fw1, const float* __restrict__ fb1,
                         float* __restrict__ out) {
    __shared__ float e[GH];
    __shared__ float h[GH];
    int b = blockIdx.x, n = threadIdx.x;
    {
        float s = 0.f;
        const float* p = g_partial + b * NFACT * GH + n;
#pragma unroll 8
        for (int j = 0; j < NFACT; j++) s += p[j * GH];
        e[n] = s;
    }
    __syncthreads();
    float acc = fb0[n];
#pragma unroll 4
    for (int k = 0; k < GH; k++) acc = fmaf(e[k], fw0[k * GH + n], acc);
    h[n] = fmaxf(acc, 0.f);
    __syncthreads();
    if (n < FOUT) {
        float a = fb1[n];
#pragma unroll 4
        for (int k = 0; k < GH; k++) a = fmaf(h[k], fw1[k * FOUT + n], a);
        out[b * FOUT + n] = a;
    }
}

// ---------------- launch ----------------------------------------------------
extern "C" void kernel_launch(void* const* d_in, const int* in_sizes, int n_in,
                              void* d_out, int out_size) {
    const float* x   = (const float*)d_in[0];
    const float* q   = (const float*)d_in[1];
    const float* gw0 = (const float*)d_in[2];
    const float* gb0 = (const float*)d_in[3];
    const float* gw1 = (const float*)d_in[4];
    const float* gb1 = (const float*)d_in[5];
    const float* gw2 = (const float*)d_in[6];
    const float* gb2 = (const float*)d_in[7];
    const float* fw0 = (const float*)d_in[8];
    const float* fb0 = (const float*)d_in[9];
    const float* fw1 = (const float*)d_in[10];
    const float* fb1 = (const float*)d_in[11];
    float* out = (float*)d_out;

    cudaFuncSetAttribute(rn_mma_kernel, cudaFuncAttributeMaxDynamicSharedMemorySize, SMEM_TOT);

    uv_kernel<<<BATCH * 2, 256>>>(x, q, gw0, gb0);
    w_half_kernel<<<dim3(8, 8, 2), dim3(32, 8)>>>(gw1, gw2);
    rn_mma_kernel<<<BATCH * NFACT, 256, SMEM_TOT>>>(gb1, gb2);
    f_kernel<<<BATCH, GH>>>(fw0, fb0, fw1, fb1, out);
}

// round 8
// speedup vs baseline: 5.0600x; 1.0842x over previous
#include <cuda_runtime.h>
#include <cuda_fp16.h>
#include <cstdint>

#define BATCH 32
#define NFACT 64
#define DOBJ  128
#define GH    256
#define FOUT  32

// ---------------- scratch (__device__ globals; no allocs allowed) ------------
__device__ float  g_Ue[BATCH * NFACT * GH];
__device__ float  g_Vv[BATCH * NFACT * GH];
__device__ float  g_partial[BATCH * NFACT * GH];
__device__ __half g_W1h[GH * GH];  // [n][k] = half(W1[k][n])
__device__ __half g_W2h[GH * GH];  // [n][k] = half(W2[k][n])

// ---------------- SMEM layout of rn_mma_kernel (halves) ----------------------
#define AS_STRIDE_H 264                    // A row stride in halves (132 words)
#define WS_STRIDE_H 40                     // W row stride in halves (20 words)
#define OFF_B1 0
#define OFF_B2 1024
#define OFF_A  2048
#define A_BYTES (64 * AS_STRIDE_H * 2)     // 33792
#define OFF_W  (OFF_A + A_BYTES)           // 35840
#define WBUF_WORDS (GH * WS_STRIDE_H / 2)  // 5120 words per buffer
#define WBUF_B (GH * WS_STRIDE_H * 2)      // 20480 B
#define SMEM_TOT (OFF_W + 3 * WBUF_B)      // 97280 B -> 2 CTAs/SM (RF-bound)
#define STG_STRIDE 260                     // epilogue-2 float staging stride

// ---------------- helpers ----------------------------------------------------
__device__ __forceinline__ uint32_t smem_u32(const void* p) {
    uint32_t a;
    asm("{ .reg .u64 t; cvta.to.shared.u64 t, %1; cvt.u32.u64 %0, t; }" : "=r"(a) : "l"(p));
    return a;
}
__device__ __forceinline__ void cp_async16(uint32_t s, const void* g) {
    asm volatile("cp.async.cg.shared.global [%0], [%1], 16;" :: "r"(s), "l"(g));
}
__device__ __forceinline__ void cp_commit() {
    asm volatile("cp.async.commit_group;" ::: "memory");
}
__device__ __forceinline__ void mma16(float c[4], const uint32_t a[4], const uint32_t b[2]) {
    asm volatile(
        "mma.sync.aligned.m16n8k16.row.col.f32.f16.f16.f32 "
        "{%0,%1,%2,%3}, {%4,%5,%6,%7}, {%8,%9}, {%0,%1,%2,%3};"
        : "+f"(c[0]), "+f"(c[1]), "+f"(c[2]), "+f"(c[3])
        : "r"(a[0]), "r"(a[1]), "r"(a[2]), "r"(a[3]), "r"(b[0]), "r"(b[1]));
}
__device__ __forceinline__ uint32_t pack_h2(float lo, float hi) {
    __half2 h = __floats2half2_rn(lo, hi);
    return *(uint32_t*)&h;
}

// ---------------- K1: prep (uv + qc fused; W1/W2 transpose->half) ------------
// blocks [0,64): uv work (b = blk>>1, part = blk&1)
// blocks [64,192): 32x32 transpose tiles of W1 (z=0) / W2 (z=1)
__global__ __launch_bounds__(256) void prep_kernel(const float* __restrict__ x,
                                                   const float* __restrict__ q,
                                                   const float* __restrict__ w0,
                                                   const float* __restrict__ b0,
                                                   const float* __restrict__ w1,
                                                   const float* __restrict__ w2) {
    __shared__ float xs[NFACT * DOBJ];  // 32 KB (transpose tile aliases this)
    __shared__ float qcs[GH];
    int tid = threadIdx.x;

    if (blockIdx.x >= 64) {
        // ---- W transpose + half convert ----
        int bid = blockIdx.x - 64;
        int z = bid >> 6, rem = bid & 63;
        int bx = (rem & 7) * 32, by = (rem >> 3) * 32;  // bx: n, by: k
        const float* in = z ? w2 : w1;
        __half* out = z ? g_W2h : g_W1h;
        float (*tile)[33] = (float (*)[33])xs;
        int tx = tid & 31, ty = tid >> 5;
#pragma unroll
        for (int r = ty; r < 32; r += 8)
            tile[r][tx] = in[(by + r) * GH + bx + tx];
        __syncthreads();
#pragma unroll
        for (int r = ty; r < 32; r += 8)
            out[(bx + r) * GH + by + tx] = __float2half_rn(tile[tx][r]);
        return;
    }

    // ---- uv work ----
    int b = blockIdx.x >> 1, part = blockIdx.x & 1;
    const float4* xb = (const float4*)(x + b * NFACT * DOBJ);
    for (int v = tid; v < NFACT * DOBJ / 4; v += 256) ((float4*)xs)[v] = xb[v];
    if (part == 0) {  // qc[col] = b0[col] + q[b] . W0[256+k][col]
        int col = tid;
        const float* qr = q + b * DOBJ;
        float acc = b0[col];
#pragma unroll 4
        for (int k = 0; k < DOBJ; k++)
            acc = fmaf(qr[k], w0[(2 * DOBJ + k) * GH + col], acc);
        qcs[col] = acc;
    }
    __syncthreads();

    int ty = tid >> 5, tx = tid & 31;
    const float* w = w0 + part * DOBJ * GH;
    float acc[8][8];
#pragma unroll
    for (int r = 0; r < 8; r++)
#pragma unroll
        for (int c = 0; c < 8; c++) acc[r][c] = 0.f;
#pragma unroll 4
    for (int k = 0; k < DOBJ; k++) {
        float a[8], bf[8];
#pragma unroll
        for (int r = 0; r < 8; r++) a[r] = xs[(ty + 8 * r) * DOBJ + k];
#pragma unroll
        for (int c = 0; c < 8; c++) bf[c] = __ldg(&w[k * GH + tx + 32 * c]);
#pragma unroll
        for (int r = 0; r < 8; r++)
#pragma unroll
            for (int c = 0; c < 8; c++) acc[r][c] = fmaf(a[r], bf[c], acc[r][c]);
    }
    float* outp = (part == 0) ? g_Ue : g_Vv;
#pragma unroll
    for (int r = 0; r < 8; r++)
#pragma unroll
        for (int c = 0; c < 8; c++) {
            float v = acc[r][c];
            if (part == 0) v += qcs[tx + 32 * c];
            outp[(b * NFACT + ty + 8 * r) * GH + tx + 32 * c] = v;
        }
}

// ---------------- K2: fp16 mma.sync fused kernel -----------------------------
// W chunk kc: halves [kc*32, kc*32+32) of every n-row of Wh[n][k]
__device__ __forceinline__ void load_w_chunk(uint32_t su, const __half* __restrict__ Wh,
                                             int kc, int buf) {
    const __half* src = Wh + kc * 32;
    uint32_t dst = su + OFF_W + buf * WBUF_B;
#pragma unroll
    for (int i = 0; i < 4; i++) {
        int p = threadIdx.x + i * 256;  // 1024 slots: 256 n-rows x 4 x 16B
        int n = p >> 2, c4 = p & 3;
        cp_async16(dst + n * (WS_STRIDE_H * 2) + c4 * 16, src + n * GH + c4 * 8);
    }
    cp_commit();
}

// one 64x256x256 fp16 GEMM over a 3-buffer W ring. Caller must have prefetched
// chunk0->buf0, chunk1->buf1. Chunk kc lives in buf kc%3; load of chunk kc+2
// into buf (kc+2)%3 is safe after this iteration's barrier (that buffer was
// last read at iteration kc-1, which every warp has finished once it passes
// the barrier). NOTE: no trailing sync — caller must __syncthreads() before
// reusing A or W regions.
__device__ __forceinline__ void gemm_mma(uint32_t su, const uint32_t* __restrict__ Au,
                                         const uint32_t* __restrict__ Wu,
                                         const __half* __restrict__ Wh,
                                         int m0, int n0, int gid, int tig,
                                         float c[2][8][4]) {
    int rb = 0;  // read buffer index = kc % 3
#pragma unroll 1
    for (int kc = 0; kc < 8; kc++) {
        if (kc < 7) asm volatile("cp.async.wait_group 1;" ::: "memory");
        else        asm volatile("cp.async.wait_group 0;" ::: "memory");
        __syncthreads();
        if (kc < 6) {
            int lb = rb + 2; if (lb >= 3) lb -= 3;
            load_w_chunk(su, Wh, kc + 2, lb);
        }
        const uint32_t* Ws = Wu + rb * WBUF_WORDS;
#pragma unroll
        for (int ks = 0; ks < 2; ks++) {  // two k16 steps per 32-k chunk
            uint32_t a[2][4];
#pragma unroll
            for (int mt = 0; mt < 2; mt++) {
                const uint32_t* ap =
                    Au + (m0 + mt * 16 + gid) * (AS_STRIDE_H / 2) + kc * 16 + ks * 8 + tig;
                a[mt][0] = ap[0];
                a[mt][1] = ap[8 * (AS_STRIDE_H / 2)];
                a[mt][2] = ap[4];
                a[mt][3] = ap[8 * (AS_STRIDE_H / 2) + 4];
            }
#pragma unroll
            for (int nt = 0; nt < 8; nt++) {
                const uint32_t* bp =
                    Ws + (n0 + nt * 8 + gid) * (WS_STRIDE_H / 2) + ks * 8 + tig;
                uint32_t bfr[2] = {bp[0], bp[4]};
                mma16(c[0][nt], a[0], bfr);
                mma16(c[1][nt], a[1], bfr);
            }
        }
        rb = (rb == 2) ? 0 : rb + 1;
    }
}

__global__ __launch_bounds__(256, 2) void rn_mma_kernel(const float* __restrict__ b1g,
                                                        const float* __restrict__ b2g) {
    extern __shared__ char smc[];
    uint32_t su = smem_u32(smc);
    __half* As = (__half*)(smc + OFF_A);
    const uint32_t* Au = (const uint32_t*)As;
    const uint32_t* Wu = (const uint32_t*)(smc + OFF_W);
    float* b1s = (float*)(smc + OFF_B1);
    float* b2s = (float*)(smc + OFF_B2);

    int tid = threadIdx.x, lane = tid & 31, wid = tid >> 5;
    int gid = lane >> 2, tig = lane & 3;
    int m0 = (wid & 1) * 32, n0 = (wid >> 1) * 64;
    int b = blockIdx.x >> 6, j = blockIdx.x & 63;

    b1s[tid] = b1g[tid];
    b2s[tid] = b2g[tid];

    // prefetch W1 chunks 0,1 into ring bufs 0,1 (independent of h0 build)
    load_w_chunk(su, g_W1h, 0, 0);
    load_w_chunk(su, g_W1h, 1, 1);

    // ---- build h0 = half(relu(Ue[b,i] + Vv[b,j])) into A ----
    // (ordered before GEMM1 reads by gemm_mma's first internal barrier)
    {
        const float4* UeB = (const float4*)(g_Ue + b * NFACT * GH);
        const float4* VvB = (const float4*)(g_Vv + (b * NFACT + j) * GH);
#pragma unroll
        for (int it = 0; it < 16; it++) {
            int p = tid + it * 256;  // 4096 slots: 64 rows x 64 float4-groups
            int i = p >> 6, c4 = p & 63;
            float4 u = UeB[i * 64 + c4];
            float4 v = VvB[c4];
            uint2 o;
            o.x = pack_h2(fmaxf(u.x + v.x, 0.f), fmaxf(u.y + v.y, 0.f));
            o.y = pack_h2(fmaxf(u.z + v.z, 0.f), fmaxf(u.w + v.w, 0.f));
            *(uint2*)((char*)smc + OFF_A + i * (AS_STRIDE_H * 2) + c4 * 8) = o;
        }
    }

    float c[2][8][4];
#pragma unroll
    for (int mt = 0; mt < 2; mt++)
#pragma unroll
        for (int nt = 0; nt < 8; nt++)
#pragma unroll
            for (int q = 0; q < 4; q++) c[mt][nt][q] = 0.f;

    // ---- GEMM1: D1 = h0 @ W1 ----
    gemm_mma(su, Au, Wu, g_W1h, m0, n0, gid, tig, c);

    // buf0 was last read at GEMM1 kc=6: every warp has passed kc=7's barrier,
    // so prefetching W2 chunk0 into buf0 is safe even before the sync below.
    load_w_chunk(su, g_W2h, 0, 0);
    __syncthreads();              // all warps done with GEMM1 (h0 reads, buf1 reads)
    load_w_chunk(su, g_W2h, 1, 1);

    // ---- epilogue1: h1 = half(relu(D1 + b1)) -> A (aliased over h0) ----
#pragma unroll
    for (int mt = 0; mt < 2; mt++)
#pragma unroll
        for (int nt = 0; nt < 8; nt++) {
            int r = m0 + mt * 16 + gid, col = n0 + nt * 8 + 2 * tig;
            float bb0 = b1s[col], bb1 = b1s[col + 1];
            *(uint32_t*)(As + r * AS_STRIDE_H + col) =
                pack_h2(fmaxf(c[mt][nt][0] + bb0, 0.f), fmaxf(c[mt][nt][1] + bb1, 0.f));
            *(uint32_t*)(As + (r + 8) * AS_STRIDE_H + col) =
                pack_h2(fmaxf(c[mt][nt][2] + bb0, 0.f), fmaxf(c[mt][nt][3] + bb1, 0.f));
            c[mt][nt][0] = c[mt][nt][1] = c[mt][nt][2] = c[mt][nt][3] = 0.f;
        }
    // h1 writes are ordered before GEMM2 reads by gemm_mma's first barrier.

    // ---- GEMM2: D2 = h1 @ W2 ----
    gemm_mma(su, Au, Wu, g_W2h, m0, n0, gid, tig, c);
    __syncthreads();  // all warps done reading As / W ring before staging reuse

    // ---- epilogue2: relu(D2 + b2) staged (A+W regions free), column sums ----
    {
        float* stg = (float*)(smc + OFF_A);  // 64 x STG_STRIDE floats
#pragma unroll
        for (int mt = 0; mt < 2; mt++)
#pragma unroll
            for (int nt = 0; nt < 8; nt++) {
                int r = m0 + mt * 16 + gid, col = n0 + nt * 8 + 2 * tig;
                float bb0 = b2s[col], bb1 = b2s[col + 1];
                stg[r * STG_STRIDE + col]           = fmaxf(c[mt][nt][0] + bb0, 0.f);
                stg[r * STG_STRIDE + col + 1]       = fmaxf(c[mt][nt][1] + bb1, 0.f);
                stg[(r + 8) * STG_STRIDE + col]     = fmaxf(c[mt][nt][2] + bb0, 0.f);
                stg[(r + 8) * STG_STRIDE + col + 1] = fmaxf(c[mt][nt][3] + bb1, 0.f);
            }
        __syncthreads();
        int n = tid;
        float s = 0.f;
#pragma unroll 8
        for (int i = 0; i < 64; i++) s += stg[i * STG_STRIDE + n];
        g_partial[(b * NFACT + j) * GH + n] = s;
    }
}

// ---------------- K3: f MLP (j-reduce fused; ILP + all-warp final layer) -----
__global__ __launch_bounds__(256) void f_kernel(const float* __restrict__ fw0,
                                                const float* __restrict__ fb0,
                                                const float* __restrict__ fw1,
                                                const float* __restrict__ fb1,
                                                float* __restrict__ out) {
    __shared__ float e[GH];
    __shared__ float h[GH];
    __shared__ float red[8 * FOUT];
    int b = blockIdx.x, tid = threadIdx.x;

    // phase A: e[n] = sum_j partial[b,j,n] (4 independent chains)
    {
        const float* p = g_partial + b * NFACT * GH + tid;
        float s0 = 0.f, s1 = 0.f, s2 = 0.f, s3 = 0.f;
#pragma unroll
        for (int j = 0; j < NFACT; j += 4) {
            s0 += p[j * GH];
            s1 += p[(j + 1) * GH];
            s2 += p[(j + 2) * GH];
            s3 += p[(j + 3) * GH];
        }
        e[tid] = (s0 + s1) + (s2 + s3);
    }
    __syncthreads();

    // phase B: h[n] = relu(e . fw0[:,n] + fb0[n])  (4 chains, unroll 16)
    {
        float a0 = 0.f, a1 = 0.f, a2 = 0.f, a3 = 0.f;
#pragma unroll 4
        for (int k = 0; k < GH; k += 4) {
            a0 = fmaf(e[k],     fw0[k * GH + tid],       a0);
            a1 = fmaf(e[k + 1], fw0[(k + 1) * GH + tid], a1);
            a2 = fmaf(e[k + 2], fw0[(k + 2) * GH + tid], a2);
            a3 = fmaf(e[k + 3], fw0[(k + 3) * GH + tid], a3);
        }
        h[tid] = fmaxf(((a0 + a1) + (a2 + a3)) + fb0[tid], 0.f);
    }
    __syncthreads();

    // phase C: out = h @ fw1 + fb1, k split across 8 warps
    {
        int w = tid >> 5, lane = tid & 31;
        float ps = 0.f;
#pragma unroll
        for (int kk = 0; kk < 32; kk++) {
            int k = w * 32 + kk;
            ps = fmaf(h[k], fw1[k * FOUT + lane], ps);
        }
        red[w * FOUT + lane] = ps;
        __syncthreads();
        if (tid < FOUT) {
            float a = fb1[tid];
#pragma unroll
            for (int t = 0; t < 8; t++) a += red[t * FOUT + tid];
            out[b * FOUT + tid] = a;
        }
    }
}

// ---------------- launch ----------------------------------------------------
extern "C" void kernel_launch(void* const* d_in, const int* in_sizes, int n_in,
                              void* d_out, int out_size) {
    const float* x   = (const float*)d_in[0];
    const float* q   = (const float*)d_in[1];
    const float* gw0 = (const float*)d_in[2];
    const float* gb0 = (const float*)d_in[3];
    const float* gw1 = (const float*)d_in[4];
    const float* gb1 = (const float*)d_in[5];
    const float* gw2 = (const float*)d_in[6];
    const float* gb2 = (const float*)d_in[7];
    const float* fw0 = (const float*)d_in[8];
    const float* fb0 = (const float*)d_in[9];
    const float* fw1 = (const float*)d_in[10];
    const float* fb1 = (const float*)d_in[11];
    float* out = (float*)d_out;

    cudaFuncSetAttribute(rn_mma_kernel, cudaFuncAttributeMaxDynamicSharedMemorySize, SMEM_TOT);

    prep_kernel<<<192, 256>>>(x, q, gw0, gb0, gw1, gw2);
    rn_mma_kernel<<<BATCH * NFACT, 256, SMEM_TOT>>>(gb1, gb2);
    f_kernel<<<BATCH, 256>>>(fw0, fb0, fw1, fb1, out);
}

// round 10
// speedup vs baseline: 5.4519x; 1.0774x over previous
#include <cuda_runtime.h>
#include <cuda_fp16.h>
#include <cstdint>

#define BATCH 32
#define NFACT 64
#define DOBJ  128
#define GH    256
#define FOUT  32

// ---------------- scratch (__device__ globals; no allocs allowed) ------------
__device__ float  g_Ue[BATCH * NFACT * GH];
__device__ float  g_Vv[BATCH * NFACT * GH];
__device__ float  g_partial[BATCH * NFACT * GH];
__device__ __half g_W1h[GH * GH];  // [n][k] = half(W1[k][n])
__device__ __half g_W2h[GH * GH];  // [n][k] = half(W2[k][n])

// ---------------- SMEM layout of rn_mma_kernel (halves) ----------------------
#define AS_STRIDE_H 264                    // A row stride in halves (132 words)
#define WS_STRIDE_H 40                     // W row stride in halves (20 words)
#define OFF_B1 0
#define OFF_B2 1024
#define OFF_A  2048
#define A_BYTES (64 * AS_STRIDE_H * 2)     // 33792
#define OFF_W  (OFF_A + A_BYTES)           // 35840
#define WBUF_WORDS (GH * WS_STRIDE_H / 2)  // 5120 words per buffer
#define WBUF_B (GH * WS_STRIDE_H * 2)      // 20480 B
#define SMEM_TOT (OFF_W + 3 * WBUF_B)      // 97280 B -> 2 CTAs/SM (RF-bound)
#define STG_STRIDE 260                     // epilogue-2 float staging stride

// ---------------- SMEM layout of prep_kernel (dynamic; floats) ---------------
// [0, 8192)        xs: x tile 64x128 (transpose branch aliases first 4.3 KB)
// [8192, 16384)    ws: W slab [k][c] 128x64
// [16384, 16640)   qred: 4x64
// [16640, 16704)   qcs: 64
#define P_XS   0
#define P_WS   8192
#define P_QRED 16384
#define P_QCS  16640
#define PREP_SMEM ((16704) * 4)            // 66816 B dynamic

// ---------------- helpers ----------------------------------------------------
__device__ __forceinline__ uint32_t smem_u32(const void* p) {
    uint32_t a;
    asm("{ .reg .u64 t; cvta.to.shared.u64 t, %1; cvt.u32.u64 %0, t; }" : "=r"(a) : "l"(p));
    return a;
}
__device__ __forceinline__ void cp_async16(uint32_t s, const void* g) {
    asm volatile("cp.async.cg.shared.global [%0], [%1], 16;" :: "r"(s), "l"(g));
}
__device__ __forceinline__ void cp_commit() {
    asm volatile("cp.async.commit_group;" ::: "memory");
}
__device__ __forceinline__ void mma16(float c[4], const uint32_t a[4], const uint32_t b[2]) {
    asm volatile(
        "mma.sync.aligned.m16n8k16.row.col.f32.f16.f16.f32 "
        "{%0,%1,%2,%3}, {%4,%5,%6,%7}, {%8,%9}, {%0,%1,%2,%3};"
        : "+f"(c[0]), "+f"(c[1]), "+f"(c[2]), "+f"(c[3])
        : "r"(a[0]), "r"(a[1]), "r"(a[2]), "r"(a[3]), "r"(b[0]), "r"(b[1]));
}
__device__ __forceinline__ uint32_t pack_h2(float lo, float hi) {
    __half2 h = __floats2half2_rn(lo, hi);
    return *(uint32_t*)&h;
}

// ---------------- K1: prep ---------------------------------------------------
// blocks [0,128): 32x32 transpose tiles of W1 (z=0) / W2 (z=1) -> half [n][k]
// blocks [128,384): uv chunk blocks. uvid = blk-128:
//   cc = uvid & 3 (64-col chunk), part = (uvid>>2) & 1, b = uvid >> 3.
//   Computes 64x64 chunk of Ue (part 0, +qc) or Vv (part 1) with W staged in SMEM.
__global__ __launch_bounds__(256) void prep_kernel(const float* __restrict__ x,
                                                   const float* __restrict__ q,
                                                   const float* __restrict__ w0,
                                                   const float* __restrict__ b0,
                                                   const float* __restrict__ w1,
                                                   const float* __restrict__ w2) {
    extern __shared__ float psm[];
    float* xs = psm + P_XS;
    float* ws = psm + P_WS;
    float* qred = psm + P_QRED;   // [4][64]
    float* qcs = psm + P_QCS;     // [64]
    int tid = threadIdx.x;

    if (blockIdx.x < 128) {
        // ---- W transpose + half convert ----
        int bid = blockIdx.x;
        int z = bid >> 6, rem = bid & 63;
        int bx = (rem & 7) * 32, by = (rem >> 3) * 32;  // bx: n, by: k
        const float* in = z ? w2 : w1;
        __half* out = z ? g_W2h : g_W1h;
        float (*tile)[33] = (float (*)[33])xs;
        int tx = tid & 31, ty = tid >> 5;
#pragma unroll
        for (int r = ty; r < 32; r += 8)
            tile[r][tx] = in[(by + r) * GH + bx + tx];
        __syncthreads();
#pragma unroll
        for (int r = ty; r < 32; r += 8)
            out[(bx + r) * GH + by + tx] = __float2half_rn(tile[tx][r]);
        return;
    }

    // ---- uv chunk ----
    int uvid = blockIdx.x - 128;
    int cc = uvid & 3, part = (uvid >> 2) & 1, b = uvid >> 3;

    // stage x[b] (64x128) and W slab (rows part*128..+128, cols cc*64..+64)
    const float4* xb = (const float4*)(x + b * NFACT * DOBJ);
#pragma unroll
    for (int i = 0; i < 8; i++) ((float4*)xs)[tid + i * 256] = xb[tid + i * 256];
    const float* wbase = w0 + part * DOBJ * GH + cc * 64;
#pragma unroll
    for (int i = 0; i < 8; i++) {
        int p = tid + i * 256;          // 2048 float4 slots: 128 rows x 16
        int row = p >> 4, c4 = p & 15;
        ((float4*)ws)[row * 16 + c4] = *(const float4*)(wbase + row * GH + c4 * 4);
    }
    if (part == 0) {  // qc for this block's 64 cols: 4 threads per col x 32 k
        int colL = tid & 63, seg = tid >> 6;
        int colG = cc * 64 + colL;
        const float* qr = q + b * DOBJ;
        float s = 0.f;
#pragma unroll 8
        for (int k = 0; k < 32; k++) {
            int kk = seg * 32 + k;
            s = fmaf(qr[kk], w0[(2 * DOBJ + kk) * GH + colG], s);
        }
        qred[seg * 64 + colL] = s;
    }
    __syncthreads();
    if (part == 0 && tid < 64) {
        qcs[tid] = b0[cc * 64 + tid] +
                   ((qred[tid] + qred[64 + tid]) + (qred[128 + tid] + qred[192 + tid]));
    }
    __syncthreads();

    int ty = tid >> 5, tx = tid & 31;
    float acc[8][2];
#pragma unroll
    for (int r = 0; r < 8; r++) { acc[r][0] = 0.f; acc[r][1] = 0.f; }
#pragma unroll 4
    for (int k = 0; k < DOBJ; k++) {
        float w0v = ws[k * 64 + tx], w1v = ws[k * 64 + tx + 32];
#pragma unroll
        for (int r = 0; r < 8; r++) {
            float a = xs[(ty + 8 * r) * DOBJ + k];
            acc[r][0] = fmaf(a, w0v, acc[r][0]);
            acc[r][1] = fmaf(a, w1v, acc[r][1]);
        }
    }
    float* outp = (part == 0) ? g_Ue : g_Vv;
#pragma unroll
    for (int r = 0; r < 8; r++) {
        int row = ty + 8 * r;
        float v0 = acc[r][0], v1 = acc[r][1];
        if (part == 0) { v0 += qcs[tx]; v1 += qcs[tx + 32]; }
        outp[(b * NFACT + row) * GH + cc * 64 + tx] = v0;
        outp[(b * NFACT + row) * GH + cc * 64 + tx + 32] = v1;
    }
}

// ---------------- K2: fp16 mma.sync fused kernel -----------------------------
// W chunk kc: halves [kc*32, kc*32+32) of every n-row of Wh[n][k]
__device__ __forceinline__ void load_w_chunk(uint32_t su, const __half* __restrict__ Wh,
                                             int kc, int buf) {
    const __half* src = Wh + kc * 32;
    uint32_t dst = su + OFF_W + buf * WBUF_B;
#pragma unroll
    for (int i = 0; i < 4; i++) {
        int p = threadIdx.x + i * 256;  // 1024 slots: 256 n-rows x 4 x 16B
        int n = p >> 2, c4 = p & 3;
        cp_async16(dst + n * (WS_STRIDE_H * 2) + c4 * 16, src + n * GH + c4 * 8);
    }
    cp_commit();
}

// one 64x256x256 fp16 GEMM over a 3-buffer W ring. Caller must have prefetched
// chunk0->buf0, chunk1->buf1. Chunk kc lives in buf kc%3; load of chunk kc+2
// into buf (kc+2)%3 is safe after this iteration's barrier (that buffer was
// last read at iteration kc-1, which every warp has finished once it passes
// the barrier). NOTE: no trailing sync — caller must __syncthreads() before
// reusing A or W regions.
__device__ __forceinline__ void gemm_mma(uint32_t su, const uint32_t* __restrict__ Au,
                                         const uint32_t* __restrict__ Wu,
                                         const __half* __restrict__ Wh,
                                         int m0, int n0, int gid, int tig,
                                         float c[2][8][4]) {
    int rb = 0;  // read buffer index = kc % 3
#pragma unroll 1
    for (int kc = 0; kc < 8; kc++) {
        if (kc < 7) asm volatile("cp.async.wait_group 1;" ::: "memory");
        else        asm volatile("cp.async.wait_group 0;" ::: "memory");
        __syncthreads();
        if (kc < 6) {
            int lb = rb + 2; if (lb >= 3) lb -= 3;
            load_w_chunk(su, Wh, kc + 2, lb);
        }
        const uint32_t* Ws = Wu + rb * WBUF_WORDS;
#pragma unroll
        for (int ks = 0; ks < 2; ks++) {  // two k16 steps per 32-k chunk
            uint32_t a[2][4];
#pragma unroll
            for (int mt = 0; mt < 2; mt++) {
                const uint32_t* ap =
                    Au + (m0 + mt * 16 + gid) * (AS_STRIDE_H / 2) + kc * 16 + ks * 8 + tig;
                a[mt][0] = ap[0];
                a[mt][1] = ap[8 * (AS_STRIDE_H / 2)];
                a[mt][2] = ap[4];
                a[mt][3] = ap[8 * (AS_STRIDE_H / 2) + 4];
            }
#pragma unroll
            for (int nt = 0; nt < 8; nt++) {
                const uint32_t* bp =
                    Ws + (n0 + nt * 8 + gid) * (WS_STRIDE_H / 2) + ks * 8 + tig;
                uint32_t bfr[2] = {bp[0], bp[4]};
                mma16(c[0][nt], a[0], bfr);
                mma16(c[1][nt], a[1], bfr);
            }
        }
        rb = (rb == 2) ? 0 : rb + 1;
    }
}

__global__ __launch_bounds__(256, 2) void rn_mma_kernel(const float* __restrict__ b1g,
                                                        const float* __restrict__ b2g) {
    extern __shared__ char smc[];
    uint32_t su = smem_u32(smc);
    __half* As = (__half*)(smc + OFF_A);
    const uint32_t* Au = (const uint32_t*)As;
    const uint32_t* Wu = (const uint32_t*)(smc + OFF_W);
    float* b1s = (float*)(smc + OFF_B1);
    float* b2s = (float*)(smc + OFF_B2);

    int tid = threadIdx.x, lane = tid & 31, wid = tid >> 5;
    int gid = lane >> 2, tig = lane & 3;
    int m0 = (wid & 1) * 32, n0 = (wid >> 1) * 64;
    int b = blockIdx.x >> 6, j = blockIdx.x & 63;

    b1s[tid] = b1g[tid];
    b2s[tid] = b2g[tid];

    // prefetch W1 chunks 0,1 into ring bufs 0,1 (independent of h0 build)
    load_w_chunk(su, g_W1h, 0, 0);
    load_w_chunk(su, g_W1h, 1, 1);

    // ---- build h0 = half(relu(Ue[b,i] + Vv[b,j])) into A ----
    // (ordered before GEMM1 reads by gemm_mma's first internal barrier)
    {
        const float4* UeB = (const float4*)(g_Ue + b * NFACT * GH);
        const float4* VvB = (const float4*)(g_Vv + (b * NFACT + j) * GH);
#pragma unroll
        for (int it = 0; it < 16; it++) {
            int p = tid + it * 256;  // 4096 slots: 64 rows x 64 float4-groups
            int i = p >> 6, c4 = p & 63;
            float4 u = UeB[i * 64 + c4];
            float4 v = VvB[c4];
            uint2 o;
            o.x = pack_h2(fmaxf(u.x + v.x, 0.f), fmaxf(u.y + v.y, 0.f));
            o.y = pack_h2(fmaxf(u.z + v.z, 0.f), fmaxf(u.w + v.w, 0.f));
            *(uint2*)((char*)smc + OFF_A + i * (AS_STRIDE_H * 2) + c4 * 8) = o;
        }
    }

    float c[2][8][4];
#pragma unroll
    for (int mt = 0; mt < 2; mt++)
#pragma unroll
        for (int nt = 0; nt < 8; nt++)
#pragma unroll
            for (int q = 0; q < 4; q++) c[mt][nt][q] = 0.f;

    // ---- GEMM1: D1 = h0 @ W1 ----
    gemm_mma(su, Au, Wu, g_W1h, m0, n0, gid, tig, c);

    // buf0 was last read at GEMM1 kc=6: every warp has passed kc=7's barrier,
    // so prefetching W2 chunk0 into buf0 is safe even before the sync below.
    load_w_chunk(su, g_W2h, 0, 0);
    __syncthreads();              // all warps done with GEMM1 (h0 reads, buf1 reads)
    load_w_chunk(su, g_W2h, 1, 1);

    // ---- epilogue1: h1 = half(relu(D1 + b1)) -> A (aliased over h0) ----
#pragma unroll
    for (int mt = 0; mt < 2; mt++)
#pragma unroll
        for (int nt = 0; nt < 8; nt++) {
            int r = m0 + mt * 16 + gid, col = n0 + nt * 8 + 2 * tig;
            float bb0 = b1s[col], bb1 = b1s[col + 1];
            *(uint32_t*)(As + r * AS_STRIDE_H + col) =
                pack_h2(fmaxf(c[mt][nt][0] + bb0, 0.f), fmaxf(c[mt][nt][1] + bb1, 0.f));
            *(uint32_t*)(As + (r + 8) * AS_STRIDE_H + col) =
                pack_h2(fmaxf(c[mt][nt][2] + bb0, 0.f), fmaxf(c[mt][nt][3] + bb1, 0.f));
            c[mt][nt][0] = c[mt][nt][1] = c[mt][nt][2] = c[mt][nt][3] = 0.f;
        }
    // h1 writes are ordered before GEMM2 reads by gemm_mma's first barrier.

    // ---- GEMM2: D2 = h1 @ W2 ----
    gemm_mma(su, Au, Wu, g_W2h, m0, n0, gid, tig, c);
    __syncthreads();  // all warps done reading As / W ring before staging reuse

    // ---- epilogue2: relu(D2 + b2) staged (A+W regions free), column sums ----
    {
        float* stg = (float*)(smc + OFF_A);  // 64 x STG_STRIDE floats
#pragma unroll
        for (int mt = 0; mt < 2; mt++)
#pragma unroll
            for (int nt = 0; nt < 8; nt++) {
                int r = m0 + mt * 16 + gid, col = n0 + nt * 8 + 2 * tig;
                float bb0 = b2s[col], bb1 = b2s[col + 1];
                stg[r * STG_STRIDE + col]           = fmaxf(c[mt][nt][0] + bb0, 0.f);
                stg[r * STG_STRIDE + col + 1]       = fmaxf(c[mt][nt][1] + bb1, 0.f);
                stg[(r + 8) * STG_STRIDE + col]     = fmaxf(c[mt][nt][2] + bb0, 0.f);
                stg[(r + 8) * STG_STRIDE + col + 1] = fmaxf(c[mt][nt][3] + bb1, 0.f);
            }
        __syncthreads();
        int n = tid;
        float s = 0.f;
#pragma unroll 8
        for (int i = 0; i < 64; i++) s += stg[i * STG_STRIDE + n];
        g_partial[(b * NFACT + j) * GH + n] = s;
    }
}

// ---------------- K3: f MLP (j-reduce fused; ILP + all-warp final layer) -----
__global__ __launch_bounds__(256) void f_kernel(const float* __restrict__ fw0,
                                                const float* __restrict__ fb0,
                                                const float* __restrict__ fw1,
                                                const float* __restrict__ fb1,
                                                float* __restrict__ out) {
    __shared__ float e[GH];
    __shared__ float h[GH];
    __shared__ float red[8 * FOUT];
    int b = blockIdx.x, tid = threadIdx.x;

    // phase A: e[n] = sum_j partial[b,j,n] (4 independent chains)
    {
        const float* p = g_partial + b * NFACT * GH + tid;
        float s0 = 0.f, s1 = 0.f, s2 = 0.f, s3 = 0.f;
#pragma unroll
        for (int j = 0; j < NFACT; j += 4) {
            s0 += p[j * GH];
            s1 += p[(j + 1) * GH];
            s2 += p[(j + 2) * GH];
            s3 += p[(j + 3) * GH];
        }
        e[tid] = (s0 + s1) + (s2 + s3);
    }
    __syncthreads();

    // phase B: h[n] = relu(e . fw0[:,n] + fb0[n])  (4 chains)
    {
        float a0 = 0.f, a1 = 0.f, a2 = 0.f, a3 = 0.f;
#pragma unroll 4
        for (int k = 0; k < GH; k += 4) {
            a0 = fmaf(e[k],     fw0[k * GH + tid],       a0);
            a1 = fmaf(e[k + 1], fw0[(k + 1) * GH + tid], a1);
            a2 = fmaf(e[k + 2], fw0[(k + 2) * GH + tid], a2);
            a3 = fmaf(e[k + 3], fw0[(k + 3) * GH + tid], a3);
        }
        h[tid] = fmaxf(((a0 + a1) + (a2 + a3)) + fb0[tid], 0.f);
    }
    __syncthreads();

    // phase C: out = h @ fw1 + fb1, k split across 8 warps
    {
        int w = tid >> 5, lane = tid & 31;
        float ps = 0.f;
#pragma unroll
        for (int kk = 0; kk < 32; kk++) {
            int k = w * 32 + kk;
            ps = fmaf(h[k], fw1[k * FOUT + lane], ps);
        }
        red[w * FOUT + lane] = ps;
        __syncthreads();
        if (tid < FOUT) {
            float a = fb1[tid];
#pragma unroll
            for (int t = 0; t < 8; t++) a += red[t * FOUT + tid];
            out[b * FOUT + tid] = a;
        }
    }
}

// ---------------- launch ----------------------------------------------------
extern "C" void kernel_launch(void* const* d_in, const int* in_sizes, int n_in,
                              void* d_out, int out_size) {
    const float* x   = (const float*)d_in[0];
    const float* q   = (const float*)d_in[1];
    const float* gw0 = (const float*)d_in[2];
    const float* gb0 = (const float*)d_in[3];
    const float* gw1 = (const float*)d_in[4];
    const float* gb1 = (const float*)d_in[5];
    const float* gw2 = (const float*)d_in[6];
    const float* gb2 = (const float*)d_in[7];
    const float* fw0 = (const float*)d_in[8];
    const float* fb0 = (const float*)d_in[9];
    const float* fw1 = (const float*)d_in[10];
    const float* fb1 = (const float*)d_in[11];
    float* out = (float*)d_out;

    cudaFuncSetAttribute(rn_mma_kernel, cudaFuncAttributeMaxDynamicSharedMemorySize, SMEM_TOT);
    cudaFuncSetAttribute(prep_kernel, cudaFuncAttributeMaxDynamicSharedMemorySize, PREP_SMEM);

    prep_kernel<<<384, 256, PREP_SMEM>>>(x, q, gw0, gb0, gw1, gw2);
    rn_mma_kernel<<<BATCH * NFACT, 256, SMEM_TOT>>>(gb1, gb2);
    f_kernel<<<BATCH, 256>>>(fw0, fb0, fw1, fb1, out);
}

// round 11
// speedup vs baseline: 5.8244x; 1.0683x over previous
#include <cuda_runtime.h>
#include <cuda_fp16.h>
#include <cstdint>

#define BATCH 32
#define NFACT 64
#define DOBJ  128
#define GH    256
#define FOUT  32

// ---------------- scratch (__device__ globals; no allocs allowed) ------------
__device__ float  g_Ue[BATCH * NFACT * GH];
__device__ float  g_Vv[BATCH * NFACT * GH];
__device__ float  g_partial[BATCH * NFACT * GH];
__device__ __half g_W1h[GH * GH];  // [n][k] = half(W1[k][n])
__device__ __half g_W2h[GH * GH];  // [n][k] = half(W2[k][n])

// ---------------- SMEM layout of rn_mma_kernel (halves) ----------------------
#define AS_STRIDE_H 264                    // A row stride in halves (132 words)
#define WS_STRIDE_H 40                     // W row stride in halves (20 words)
#define OFF_B1 0
#define OFF_B2 1024
#define OFF_RED 2048                       // [2][2][256] floats = 4096 B
#define OFF_A  6144
#define A_BYTES (128 * AS_STRIDE_H * 2)    // 67584 (M=128 rows)
#define OFF_W  (OFF_A + A_BYTES)           // 73728
#define WBUF_WORDS (GH * WS_STRIDE_H / 2)  // 5120 words per buffer
#define WBUF_B (GH * WS_STRIDE_H * 2)      // 20480 B
#define SMEM_TOT (OFF_W + 3 * WBUF_B)      // 135168 B -> 1 CTA/SM (RF-bound anyway)

// ---------------- SMEM layout of prep_kernel (dynamic; floats) ---------------
#define P_XS   0
#define P_WS   8192
#define P_QRED 16384
#define P_QCS  16640
#define PREP_SMEM ((16704) * 4)            // 66816 B dynamic

// ---------------- helpers ----------------------------------------------------
__device__ __forceinline__ uint32_t smem_u32(const void* p) {
    uint32_t a;
    asm("{ .reg .u64 t; cvta.to.shared.u64 t, %1; cvt.u32.u64 %0, t; }" : "=r"(a) : "l"(p));
    return a;
}
__device__ __forceinline__ void cp_async16(uint32_t s, const void* g) {
    asm volatile("cp.async.cg.shared.global [%0], [%1], 16;" :: "r"(s), "l"(g));
}
__device__ __forceinline__ void cp_commit() {
    asm volatile("cp.async.commit_group;" ::: "memory");
}
__device__ __forceinline__ void mma16(float c[4], const uint32_t a[4], const uint32_t b[2]) {
    asm volatile(
        "mma.sync.aligned.m16n8k16.row.col.f32.f16.f16.f32 "
        "{%0,%1,%2,%3}, {%4,%5,%6,%7}, {%8,%9}, {%0,%1,%2,%3};"
        : "+f"(c[0]), "+f"(c[1]), "+f"(c[2]), "+f"(c[3])
        : "r"(a[0]), "r"(a[1]), "r"(a[2]), "r"(a[3]), "r"(b[0]), "r"(b[1]));
}
__device__ __forceinline__ uint32_t pack_h2(float lo, float hi) {
    __half2 h = __floats2half2_rn(lo, hi);
    return *(uint32_t*)&h;
}

// ---------------- K1: prep (unchanged from R10) ------------------------------
__global__ __launch_bounds__(256) void prep_kernel(const float* __restrict__ x,
                                                   const float* __restrict__ q,
                                                   const float* __restrict__ w0,
                                                   const float* __restrict__ b0,
                                                   const float* __restrict__ w1,
                                                   const float* __restrict__ w2) {
    extern __shared__ float psm[];
    float* xs = psm + P_XS;
    float* ws = psm + P_WS;
    float* qred = psm + P_QRED;
    float* qcs = psm + P_QCS;
    int tid = threadIdx.x;

    if (blockIdx.x < 128) {
        int bid = blockIdx.x;
        int z = bid >> 6, rem = bid & 63;
        int bx = (rem & 7) * 32, by = (rem >> 3) * 32;
        const float* in = z ? w2 : w1;
        __half* out = z ? g_W2h : g_W1h;
        float (*tile)[33] = (float (*)[33])xs;
        int tx = tid & 31, ty = tid >> 5;
#pragma unroll
        for (int r = ty; r < 32; r += 8)
            tile[r][tx] = in[(by + r) * GH + bx + tx];
        __syncthreads();
#pragma unroll
        for (int r = ty; r < 32; r += 8)
            out[(bx + r) * GH + by + tx] = __float2half_rn(tile[tx][r]);
        return;
    }

    int uvid = blockIdx.x - 128;
    int cc = uvid & 3, part = (uvid >> 2) & 1, b = uvid >> 3;

    const float4* xb = (const float4*)(x + b * NFACT * DOBJ);
#pragma unroll
    for (int i = 0; i < 8; i++) ((float4*)xs)[tid + i * 256] = xb[tid + i * 256];
    const float* wbase = w0 + part * DOBJ * GH + cc * 64;
#pragma unroll
    for (int i = 0; i < 8; i++) {
        int p = tid + i * 256;
        int row = p >> 4, c4 = p & 15;
        ((float4*)ws)[row * 16 + c4] = *(const float4*)(wbase + row * GH + c4 * 4);
    }
    if (part == 0) {
        int colL = tid & 63, seg = tid >> 6;
        int colG = cc * 64 + colL;
        const float* qr = q + b * DOBJ;
        float s = 0.f;
#pragma unroll 8
        for (int k = 0; k < 32; k++) {
            int kk = seg * 32 + k;
            s = fmaf(qr[kk], w0[(2 * DOBJ + kk) * GH + colG], s);
        }
        qred[seg * 64 + colL] = s;
    }
    __syncthreads();
    if (part == 0 && tid < 64) {
        qcs[tid] = b0[cc * 64 + tid] +
                   ((qred[tid] + qred[64 + tid]) + (qred[128 + tid] + qred[192 + tid]));
    }
    __syncthreads();

    int ty = tid >> 5, tx = tid & 31;
    float acc[8][2];
#pragma unroll
    for (int r = 0; r < 8; r++) { acc[r][0] = 0.f; acc[r][1] = 0.f; }
#pragma unroll 4
    for (int k = 0; k < DOBJ; k++) {
        float w0v = ws[k * 64 + tx], w1v = ws[k * 64 + tx + 32];
#pragma unroll
        for (int r = 0; r < 8; r++) {
            float a = xs[(ty + 8 * r) * DOBJ + k];
            acc[r][0] = fmaf(a, w0v, acc[r][0]);
            acc[r][1] = fmaf(a, w1v, acc[r][1]);
        }
    }
    float* outp = (part == 0) ? g_Ue : g_Vv;
#pragma unroll
    for (int r = 0; r < 8; r++) {
        int row = ty + 8 * r;
        float v0 = acc[r][0], v1 = acc[r][1];
        if (part == 0) { v0 += qcs[tx]; v1 += qcs[tx + 32]; }
        outp[(b * NFACT + row) * GH + cc * 64 + tx] = v0;
        outp[(b * NFACT + row) * GH + cc * 64 + tx + 32] = v1;
    }
}

// ---------------- K2: fp16 mma.sync fused kernel (M=128, 512 thr) ------------
__device__ __forceinline__ void load_w_chunk(uint32_t su, const __half* __restrict__ Wh,
                                             int kc, int buf) {
    const __half* src = Wh + kc * 32;
    uint32_t dst = su + OFF_W + buf * WBUF_B;
#pragma unroll
    for (int i = 0; i < 2; i++) {
        int p = threadIdx.x + i * 512;  // 1024 slots: 256 n-rows x 4 x 16B
        int n = p >> 2, c4 = p & 3;
        cp_async16(dst + n * (WS_STRIDE_H * 2) + c4 * 16, src + n * GH + c4 * 8);
    }
    cp_commit();
}

// one 128x256x256 fp16 GEMM over a 3-buffer W ring (same hazard proof as R10:
// buffer kc%3 reloaded at iteration kc, last read at kc-1, gated by barrier).
// No trailing sync — caller must __syncthreads() before reusing A or W.
__device__ __forceinline__ void gemm_mma(uint32_t su, const uint32_t* __restrict__ Au,
                                         const uint32_t* __restrict__ Wu,
                                         const __half* __restrict__ Wh,
                                         int m0, int n0, int gid, int tig,
                                         float c[2][8][4]) {
    int rb = 0;
#pragma unroll 1
    for (int kc = 0; kc < 8; kc++) {
        if (kc < 7) asm volatile("cp.async.wait_group 1;" ::: "memory");
        else        asm volatile("cp.async.wait_group 0;" ::: "memory");
        __syncthreads();
        if (kc < 6) {
            int lb = rb + 2; if (lb >= 3) lb -= 3;
            load_w_chunk(su, Wh, kc + 2, lb);
        }
        const uint32_t* Ws = Wu + rb * WBUF_WORDS;
#pragma unroll
        for (int ks = 0; ks < 2; ks++) {
            uint32_t a[2][4];
#pragma unroll
            for (int mt = 0; mt < 2; mt++) {
                const uint32_t* ap =
                    Au + (m0 + mt * 16 + gid) * (AS_STRIDE_H / 2) + kc * 16 + ks * 8 + tig;
                a[mt][0] = ap[0];
                a[mt][1] = ap[8 * (AS_STRIDE_H / 2)];
                a[mt][2] = ap[4];
                a[mt][3] = ap[8 * (AS_STRIDE_H / 2) + 4];
            }
#pragma unroll
            for (int nt = 0; nt < 8; nt++) {
                const uint32_t* bp =
                    Ws + (n0 + nt * 8 + gid) * (WS_STRIDE_H / 2) + ks * 8 + tig;
                uint32_t bfr[2] = {bp[0], bp[4]};
                mma16(c[0][nt], a[0], bfr);
                mma16(c[1][nt], a[1], bfr);
            }
        }
        rb = (rb == 2) ? 0 : rb + 1;
    }
}

__global__ __launch_bounds__(512, 1) void rn_mma_kernel(const float* __restrict__ b1g,
                                                        const float* __restrict__ b2g) {
    extern __shared__ char smc[];
    uint32_t su = smem_u32(smc);
    __half* As = (__half*)(smc + OFF_A);
    const uint32_t* Au = (const uint32_t*)As;
    const uint32_t* Wu = (const uint32_t*)(smc + OFF_W);
    float* b1s = (float*)(smc + OFF_B1);
    float* b2s = (float*)(smc + OFF_B2);
    float* red = (float*)(smc + OFF_RED);  // [2 j][2 sub][256 cols]

    int tid = threadIdx.x, lane = tid & 31, wid = tid >> 5;
    int gid = lane >> 2, tig = lane & 3;
    int mw = wid & 3, nw = wid >> 2;
    int m0 = mw * 32, n0 = nw * 64;
    int b = blockIdx.x >> 5, jp = blockIdx.x & 31;  // j-pair: j = 2*jp + {0,1}

    if (tid < GH) {
        b1s[tid] = b1g[tid];
        b2s[tid] = b2g[tid];
    }

    // prefetch W1 chunks 0,1 into ring bufs 0,1 (independent of h0 build)
    load_w_chunk(su, g_W1h, 0, 0);
    load_w_chunk(su, g_W1h, 1, 1);

    // ---- build h0: rows [0,64) = (j0, i), rows [64,128) = (j1, i) ----
    // (ordered before GEMM1 reads by gemm_mma's first internal barrier)
    {
        const float4* UeB = (const float4*)(g_Ue + b * NFACT * GH);
        const float4* VvB = (const float4*)(g_Vv + (b * NFACT + 2 * jp) * GH);
#pragma unroll
        for (int it = 0; it < 16; it++) {
            int p = tid + it * 512;  // 8192 slots: 128 rows x 64 float4-groups
            int r = p >> 6, c4 = p & 63;
            int i = r & 63, jl = r >> 6;
            float4 u = UeB[i * 64 + c4];
            float4 v = VvB[jl * 64 + c4];
            uint2 o;
            o.x = pack_h2(fmaxf(u.x + v.x, 0.f), fmaxf(u.y + v.y, 0.f));
            o.y = pack_h2(fmaxf(u.z + v.z, 0.f), fmaxf(u.w + v.w, 0.f));
            *(uint2*)((char*)smc + OFF_A + r * (AS_STRIDE_H * 2) + c4 * 8) = o;
        }
    }

    float c[2][8][4];
#pragma unroll
    for (int mt = 0; mt < 2; mt++)
#pragma unroll
        for (int nt = 0; nt < 8; nt++)
#pragma unroll
            for (int q = 0; q < 4; q++) c[mt][nt][q] = 0.f;

    // ---- GEMM1: D1 = h0 @ W1 ----
    gemm_mma(su, Au, Wu, g_W1h, m0, n0, gid, tig, c);

    // buf0 free (last read kc=6, gated by kc=7 barrier); then full sync; buf1.
    load_w_chunk(su, g_W2h, 0, 0);
    __syncthreads();
    load_w_chunk(su, g_W2h, 1, 1);

    // ---- epilogue1: h1 = half(relu(D1 + b1)) -> A (aliased over h0) ----
#pragma unroll
    for (int mt = 0; mt < 2; mt++)
#pragma unroll
        for (int nt = 0; nt < 8; nt++) {
            int r = m0 + mt * 16 + gid, col = n0 + nt * 8 + 2 * tig;
            float bb0 = b1s[col], bb1 = b1s[col + 1];
            *(uint32_t*)(As + r * AS_STRIDE_H + col) =
                pack_h2(fmaxf(c[mt][nt][0] + bb0, 0.f), fmaxf(c[mt][nt][1] + bb1, 0.f));
            *(uint32_t*)(As + (r + 8) * AS_STRIDE_H + col) =
                pack_h2(fmaxf(c[mt][nt][2] + bb0, 0.f), fmaxf(c[mt][nt][3] + bb1, 0.f));
            c[mt][nt][0] = c[mt][nt][1] = c[mt][nt][2] = c[mt][nt][3] = 0.f;
        }
    // h1 writes ordered before GEMM2 reads by gemm_mma's first barrier.

    // ---- GEMM2: D2 = h1 @ W2 ----
    gemm_mma(su, Au, Wu, g_W2h, m0, n0, gid, tig, c);

    // ---- epilogue2: relu(D2 + b2), shuffle-reduce column sums over i ----
    // Warp mw covers rows [m0, m0+32) -- entirely within j-half (mw>>1).
    {
        int jl = mw >> 1, sub = mw & 1;
#pragma unroll
        for (int nt = 0; nt < 8; nt++) {
            int col = n0 + nt * 8 + 2 * tig;
            float bb0 = b2s[col], bb1 = b2s[col + 1];
            // this thread's 4 rows of the warp's 32
            float s0 = fmaxf(c[0][nt][0] + bb0, 0.f) + fmaxf(c[0][nt][2] + bb0, 0.f) +
                       fmaxf(c[1][nt][0] + bb0, 0.f) + fmaxf(c[1][nt][2] + bb0, 0.f);
            float s1 = fmaxf(c[0][nt][1] + bb1, 0.f) + fmaxf(c[0][nt][3] + bb1, 0.f) +
                       fmaxf(c[1][nt][1] + bb1, 0.f) + fmaxf(c[1][nt][3] + bb1, 0.f);
            // sum over gid (lane bits 2..4)
#pragma unroll
            for (int msk = 4; msk <= 16; msk <<= 1) {
                s0 += __shfl_xor_sync(0xFFFFFFFF, s0, msk);
                s1 += __shfl_xor_sync(0xFFFFFFFF, s1, msk);
            }
            if (gid == 0) {
                red[(jl * 2 + sub) * GH + col] = s0;
                red[(jl * 2 + sub) * GH + col + 1] = s1;
            }
        }
        __syncthreads();
        int jl2 = tid >> 8, col = tid & 255;
        g_partial[(b * NFACT + 2 * jp + jl2) * GH + col] =
            red[(jl2 * 2) * GH + col] + red[(jl2 * 2 + 1) * GH + col];
    }
}

// ---------------- K3: f MLP (j-reduce fused; 8-chain ILP) --------------------
__global__ __launch_bounds__(256) void f_kernel(const float* __restrict__ fw0,
                                                const float* __restrict__ fb0,
                                                const float* __restrict__ fw1,
                                                const float* __restrict__ fb1,
                                                float* __restrict__ out) {
    __shared__ float e[GH];
    __shared__ float h[GH];
    __shared__ float red[8 * FOUT];
    int b = blockIdx.x, tid = threadIdx.x;

    // phase A: e[n] = sum_j partial[b,j,n] (8 chains)
    {
        const float* p = g_partial + b * NFACT * GH + tid;
        float s[8];
#pragma unroll
        for (int u = 0; u < 8; u++) s[u] = 0.f;
#pragma unroll
        for (int j = 0; j < NFACT; j += 8)
#pragma unroll
            for (int u = 0; u < 8; u++) s[u] += p[(j + u) * GH];
        e[tid] = ((s[0] + s[1]) + (s[2] + s[3])) + ((s[4] + s[5]) + (s[6] + s[7]));
    }
    __syncthreads();

    // phase B: h[n] = relu(e . fw0[:,n] + fb0[n]) (8 chains)
    {
        float a[8];
#pragma unroll
        for (int u = 0; u < 8; u++) a[u] = 0.f;
#pragma unroll 4
        for (int k = 0; k < GH; k += 8)
#pragma unroll
            for (int u = 0; u < 8; u++)
                a[u] = fmaf(e[k + u], fw0[(k + u) * GH + tid], a[u]);
        float t = ((a[0] + a[1]) + (a[2] + a[3])) + ((a[4] + a[5]) + (a[6] + a[7]));
        h[tid] = fmaxf(t + fb0[tid], 0.f);
    }
    __syncthreads();

    // phase C: out = h @ fw1 + fb1, k split across 8 warps
    {
        int w = tid >> 5, lane = tid & 31;
        float ps = 0.f;
#pragma unroll
        for (int kk = 0; kk < 32; kk++) {
            int k = w * 32 + kk;
            ps = fmaf(h[k], fw1[k * FOUT + lane], ps);
        }
        red[w * FOUT + lane] = ps;
        __syncthreads();
        if (tid < FOUT) {
            float a = fb1[tid];
#pragma unroll
            for (int t = 0; t < 8; t++) a += red[t * FOUT + tid];
            out[b * FOUT + tid] = a;
        }
    }
}

// ---------------- launch ----------------------------------------------------
extern "C" void kernel_launch(void* const* d_in, const int* in_sizes, int n_in,
                              void* d_out, int out_size) {
    const float* x   = (const float*)d_in[0];
    const float* q   = (const float*)d_in[1];
    const float* gw0 = (const float*)d_in[2];
    const float* gb0 = (const float*)d_in[3];
    const float* gw1 = (const float*)d_in[4];
    const float* gb1 = (const float*)d_in[5];
    const float* gw2 = (const float*)d_in[6];
    const float* gb2 = (const float*)d_in[7];
    const float* fw0 = (const float*)d_in[8];
    const float* fb0 = (const float*)d_in[9];
    const float* fw1 = (const float*)d_in[10];
    const float* fb1 = (const float*)d_in[11];
    float* out = (float*)d_out;

    cudaFuncSetAttribute(rn_mma_kernel, cudaFuncAttributeMaxDynamicSharedMemorySize, SMEM_TOT);
    cudaFuncSetAttribute(prep_kernel, cudaFuncAttributeMaxDynamicSharedMemorySize, PREP_SMEM);

    prep_kernel<<<384, 256, PREP_SMEM>>>(x, q, gw0, gb0, gw1, gw2);
    rn_mma_kernel<<<BATCH * NFACT / 2, 512, SMEM_TOT>>>(gb1, gb2);
    f_kernel<<<BATCH, 256>>>(fw0, fb0, fw1, fb1, out);
}

// round 12
// speedup vs baseline: 6.4498x; 1.1074x over previous
#include <cuda_runtime.h>
#include <cuda_fp16.h>
#include <cstdint>

#define BATCH 32
#define NFACT 64
#define DOBJ  128
#define GH    256
#define FOUT  32

// ---------------- scratch (__device__ globals; no allocs allowed) ------------
__device__ float  g_Ue[BATCH * NFACT * GH];
__device__ float  g_Vv[BATCH * NFACT * GH];
__device__ float  g_emb[BATCH * GH];      // atomically accumulated embedding
__device__ __half g_W1h[GH * GH];         // [n][k] = half(W1[k][n])
__device__ __half g_W2h[GH * GH];         // [n][k] = half(W2[k][n])

// ---------------- SMEM layout of rn_mma_kernel -------------------------------
#define AS_STRIDE_H 264                    // A row stride in halves (132 words)
#define WROW_B 144                         // W row: 64 halves (128 B) + 16 B pad
#define OFF_B1 0
#define OFF_B2 1024
#define OFF_RED 2048                       // [4][256] floats = 4096 B
#define OFF_A  6144
#define A_BYTES (128 * AS_STRIDE_H * 2)    // 67584 (M=128 rows)
#define OFF_W  (OFF_A + A_BYTES)           // 73728
#define WBUF_WORDS (GH * WROW_B / 4)       // 9216 words per buffer
#define WBUF_B (GH * WROW_B)               // 36864 B (64-k chunk, 256 n-rows)
#define SMEM_TOT (OFF_W + 3 * WBUF_B)      // 184320 B -> 1 CTA/SM

// ---------------- SMEM layout of prep_kernel (dynamic; floats) ---------------
#define P_XS   0
#define P_WS   8192
#define P_QRED 16384
#define P_QCS  16640
#define PREP_SMEM ((16704) * 4)            // 66816 B dynamic

// ---------------- helpers ----------------------------------------------------
__device__ __forceinline__ uint32_t smem_u32(const void* p) {
    uint32_t a;
    asm("{ .reg .u64 t; cvta.to.shared.u64 t, %1; cvt.u32.u64 %0, t; }" : "=r"(a) : "l"(p));
    return a;
}
__device__ __forceinline__ void cp_async16(uint32_t s, const void* g) {
    asm volatile("cp.async.cg.shared.global [%0], [%1], 16;" :: "r"(s), "l"(g));
}
__device__ __forceinline__ void cp_commit() {
    asm volatile("cp.async.commit_group;" ::: "memory");
}
__device__ __forceinline__ void mma16(float c[4], const uint32_t a[4], const uint32_t b[2]) {
    asm volatile(
        "mma.sync.aligned.m16n8k16.row.col.f32.f16.f16.f32 "
        "{%0,%1,%2,%3}, {%4,%5,%6,%7}, {%8,%9}, {%0,%1,%2,%3};"
        : "+f"(c[0]), "+f"(c[1]), "+f"(c[2]), "+f"(c[3])
        : "r"(a[0]), "r"(a[1]), "r"(a[2]), "r"(a[3]), "r"(b[0]), "r"(b[1]));
}
__device__ __forceinline__ uint32_t pack_h2(float lo, float hi) {
    __half2 h = __floats2half2_rn(lo, hi);
    return *(uint32_t*)&h;
}

// ---------------- K1: prep ---------------------------------------------------
// blocks [0,128): transpose W1/W2 -> half [n][k]; blocks [0,8) also zero g_emb.
// blocks [128,384): uv 64x64 chunks with W slab in SMEM, k-vectorized loop.
__global__ __launch_bounds__(256) void prep_kernel(const float* __restrict__ x,
                                                   const float* __restrict__ q,
                                                   const float* __restrict__ w0,
                                                   const float* __restrict__ b0,
                                                   const float* __restrict__ w1,
                                                   const float* __restrict__ w2) {
    extern __shared__ float psm[];
    float* xs = psm + P_XS;
    float* ws = psm + P_WS;
    float* qred = psm + P_QRED;
    float* qcs = psm + P_QCS;
    int tid = threadIdx.x;

    if (blockIdx.x < 128) {
        if (blockIdx.x < 8) {  // zero g_emb (8 blocks x 256 thr x 4 floats)
            float4 z = {0.f, 0.f, 0.f, 0.f};
            *(float4*)&g_emb[(blockIdx.x * 256 + tid) * 4] = z;
        }
        int bid = blockIdx.x;
        int z = bid >> 6, rem = bid & 63;
        int bx = (rem & 7) * 32, by = (rem >> 3) * 32;
        const float* in = z ? w2 : w1;
        __half* out = z ? g_W2h : g_W1h;
        float (*tile)[33] = (float (*)[33])xs;
        int tx = tid & 31, ty = tid >> 5;
#pragma unroll
        for (int r = ty; r < 32; r += 8)
            tile[r][tx] = in[(by + r) * GH + bx + tx];
        __syncthreads();
#pragma unroll
        for (int r = ty; r < 32; r += 8)
            out[(bx + r) * GH + by + tx] = __float2half_rn(tile[tx][r]);
        return;
    }

    int uvid = blockIdx.x - 128;
    int cc = uvid & 3, part = (uvid >> 2) & 1, b = uvid >> 3;

    const float4* xb = (const float4*)(x + b * NFACT * DOBJ);
#pragma unroll
    for (int i = 0; i < 8; i++) ((float4*)xs)[tid + i * 256] = xb[tid + i * 256];
    const float* wbase = w0 + part * DOBJ * GH + cc * 64;
#pragma unroll
    for (int i = 0; i < 8; i++) {
        int p = tid + i * 256;
        int row = p >> 4, c4 = p & 15;
        ((float4*)ws)[row * 16 + c4] = *(const float4*)(wbase + row * GH + c4 * 4);
    }
    if (part == 0) {
        int colL = tid & 63, seg = tid >> 6;
        int colG = cc * 64 + colL;
        const float* qr = q + b * DOBJ;
        float s = 0.f;
#pragma unroll 8
        for (int k = 0; k < 32; k++) {
            int kk = seg * 32 + k;
            s = fmaf(qr[kk], w0[(2 * DOBJ + kk) * GH + colG], s);
        }
        qred[seg * 64 + colL] = s;
    }
    __syncthreads();
    if (part == 0 && tid < 64) {
        qcs[tid] = b0[cc * 64 + tid] +
                   ((qred[tid] + qred[64 + tid]) + (qred[128 + tid] + qred[192 + tid]));
    }
    __syncthreads();

    int ty = tid >> 5, tx = tid & 31;
    const float4* xs4 = (const float4*)xs;
    float acc[8][2];
#pragma unroll
    for (int r = 0; r < 8; r++) { acc[r][0] = 0.f; acc[r][1] = 0.f; }
#pragma unroll 2
    for (int k4 = 0; k4 < 32; k4++) {
        float4 a4[8];
#pragma unroll
        for (int r = 0; r < 8; r++) a4[r] = xs4[(ty + 8 * r) * 32 + k4];
        float wv[4][2];
#pragma unroll
        for (int kk = 0; kk < 4; kk++) {
            wv[kk][0] = ws[(4 * k4 + kk) * 64 + tx];
            wv[kk][1] = ws[(4 * k4 + kk) * 64 + tx + 32];
        }
#pragma unroll
        for (int r = 0; r < 8; r++) {
            acc[r][0] = fmaf(a4[r].x, wv[0][0], acc[r][0]);
            acc[r][1] = fmaf(a4[r].x, wv[0][1], acc[r][1]);
            acc[r][0] = fmaf(a4[r].y, wv[1][0], acc[r][0]);
            acc[r][1] = fmaf(a4[r].y, wv[1][1], acc[r][1]);
            acc[r][0] = fmaf(a4[r].z, wv[2][0], acc[r][0]);
            acc[r][1] = fmaf(a4[r].z, wv[2][1], acc[r][1]);
            acc[r][0] = fmaf(a4[r].w, wv[3][0], acc[r][0]);
            acc[r][1] = fmaf(a4[r].w, wv[3][1], acc[r][1]);
        }
    }
    float* outp = (part == 0) ? g_Ue : g_Vv;
#pragma unroll
    for (int r = 0; r < 8; r++) {
        int row = ty + 8 * r;
        float v0 = acc[r][0], v1 = acc[r][1];
        if (part == 0) { v0 += qcs[tx]; v1 += qcs[tx + 32]; }
        outp[(b * NFACT + row) * GH + cc * 64 + tx] = v0;
        outp[(b * NFACT + row) * GH + cc * 64 + tx + 32] = v1;
    }
}

// ---------------- K2: fp16 mma.sync fused kernel (M=128, 64-k chunks) --------
// W chunk kc: halves [kc*64, kc*64+64) of every n-row of Wh[n][k]
__device__ __forceinline__ void load_w_chunk(uint32_t su, const __half* __restrict__ Wh,
                                             int kc, int buf) {
    const __half* src = Wh + kc * 64;
    uint32_t dst = su + OFF_W + buf * WBUF_B;
#pragma unroll
    for (int i = 0; i < 4; i++) {
        int p = threadIdx.x + i * 512;  // 2048 slots: 256 n-rows x 8 x 16B
        int n = p >> 3, c4 = p & 7;
        cp_async16(dst + n * WROW_B + c4 * 16, src + n * GH + c4 * 8);
    }
    cp_commit();
}

// one 128x256x256 fp16 GEMM: 4 chunks of k=64 over a 3-buffer ring.
// Chunk c lives in buf (sb+c)%3; caller prefetched c0,c1. In-loop, chunk kc+2
// is loaded into buf (sb+kc+2)%3 at iteration kc (kc<2): that buffer was last
// read at iteration kc-1, and the barrier at top of kc guarantees all warps
// finished kc-1's compute. wait_group ledger: commits = pre(c0,c1) + kc0(c2) +
// kc1(c3); waits: kc<3 wait<=1 (guarantees chunk kc resident), kc=3 wait 0.
// No trailing sync — caller must __syncthreads() before reusing A or W.
__device__ __forceinline__ void gemm_mma(uint32_t su, const uint32_t* __restrict__ Au,
                                         const uint32_t* __restrict__ Wu,
                                         const __half* __restrict__ Wh, int sb,
                                         int m0, int n0, int gid, int tig,
                                         float c[2][8][4]) {
#pragma unroll 1
    for (int kc = 0; kc < 4; kc++) {
        if (kc < 3) asm volatile("cp.async.wait_group 1;" ::: "memory");
        else        asm volatile("cp.async.wait_group 0;" ::: "memory");
        __syncthreads();
        if (kc < 2) load_w_chunk(su, Wh, kc + 2, (sb + kc + 2) % 3);
        const uint32_t* Ws = Wu + ((sb + kc) % 3) * WBUF_WORDS;
#pragma unroll
        for (int ks = 0; ks < 4; ks++) {  // four k16 steps per 64-k chunk
            uint32_t a[2][4];
#pragma unroll
            for (int mt = 0; mt < 2; mt++) {
                const uint32_t* ap =
                    Au + (m0 + mt * 16 + gid) * (AS_STRIDE_H / 2) + kc * 32 + ks * 8 + tig;
                a[mt][0] = ap[0];
                a[mt][1] = ap[8 * (AS_STRIDE_H / 2)];
                a[mt][2] = ap[4];
                a[mt][3] = ap[8 * (AS_STRIDE_H / 2) + 4];
            }
#pragma unroll
            for (int nt = 0; nt < 8; nt++) {
                const uint32_t* bp =
                    Ws + (n0 + nt * 8 + gid) * (WROW_B / 4) + ks * 8 + tig;
                uint32_t bfr[2] = {bp[0], bp[4]};
                mma16(c[0][nt], a[0], bfr);
                mma16(c[1][nt], a[1], bfr);
            }
        }
    }
}

__global__ __launch_bounds__(512, 1) void rn_mma_kernel(const float* __restrict__ b1g,
                                                        const float* __restrict__ b2g) {
    extern __shared__ char smc[];
    uint32_t su = smem_u32(smc);
    __half* As = (__half*)(smc + OFF_A);
    const uint32_t* Au = (const uint32_t*)As;
    const uint32_t* Wu = (const uint32_t*)(smc + OFF_W);
    float* b1s = (float*)(smc + OFF_B1);
    float* b2s = (float*)(smc + OFF_B2);
    float* red = (float*)(smc + OFF_RED);  // [4][256]

    int tid = threadIdx.x, lane = tid & 31, wid = tid >> 5;
    int gid = lane >> 2, tig = lane & 3;
    int mw = wid & 3, nw = wid >> 2;
    int m0 = mw * 32, n0 = nw * 64;
    int b = blockIdx.x >> 5, jp = blockIdx.x & 31;

    if (tid < GH) {
        b1s[tid] = b1g[tid];
        b2s[tid] = b2g[tid];
    }

    // prefetch W1 chunks 0,1 -> bufs 0,1 (sb=0)
    load_w_chunk(su, g_W1h, 0, 0);
    load_w_chunk(su, g_W1h, 1, 1);

    // ---- build h0: rows [0,64) = (j0, i), rows [64,128) = (j1, i) ----
    {
        const float4* UeB = (const float4*)(g_Ue + b * NFACT * GH);
        const float4* VvB = (const float4*)(g_Vv + (b * NFACT + 2 * jp) * GH);
#pragma unroll
        for (int it = 0; it < 16; it++) {
            int p = tid + it * 512;
            int r = p >> 6, c4 = p & 63;
            int i = r & 63, jl = r >> 6;
            float4 u = UeB[i * 64 + c4];
            float4 v = VvB[jl * 64 + c4];
            uint2 o;
            o.x = pack_h2(fmaxf(u.x + v.x, 0.f), fmaxf(u.y + v.y, 0.f));
            o.y = pack_h2(fmaxf(u.z + v.z, 0.f), fmaxf(u.w + v.w, 0.f));
            *(uint2*)((char*)smc + OFF_A + r * (AS_STRIDE_H * 2) + c4 * 8) = o;
        }
    }

    float c[2][8][4];
#pragma unroll
    for (int mt = 0; mt < 2; mt++)
#pragma unroll
        for (int nt = 0; nt < 8; nt++)
#pragma unroll
            for (int q = 0; q < 4; q++) c[mt][nt][q] = 0.f;

    // ---- GEMM1: D1 = h0 @ W1 (sb=0) ----
    gemm_mma(su, Au, Wu, g_W1h, 0, m0, n0, gid, tig, c);

    // W2 c0 -> buf1: buf1 last read at G1 kc=1; every returned warp passed the
    // kc=3 barrier (=> all warps finished kc<=2 compute), so buf1 is free.
    load_w_chunk(su, g_W2h, 0, 1);
    __syncthreads();  // all warps done with GEMM1 (h0 + buf0 reads)
    load_w_chunk(su, g_W2h, 1, 2);

    // ---- epilogue1: h1 = half(relu(D1 + b1)) -> A (aliased over h0) ----
#pragma unroll
    for (int mt = 0; mt < 2; mt++)
#pragma unroll
        for (int nt = 0; nt < 8; nt++) {
            int r = m0 + mt * 16 + gid, col = n0 + nt * 8 + 2 * tig;
            float bb0 = b1s[col], bb1 = b1s[col + 1];
            *(uint32_t*)(As + r * AS_STRIDE_H + col) =
                pack_h2(fmaxf(c[mt][nt][0] + bb0, 0.f), fmaxf(c[mt][nt][1] + bb1, 0.f));
            *(uint32_t*)(As + (r + 8) * AS_STRIDE_H + col) =
                pack_h2(fmaxf(c[mt][nt][2] + bb0, 0.f), fmaxf(c[mt][nt][3] + bb1, 0.f));
            c[mt][nt][0] = c[mt][nt][1] = c[mt][nt][2] = c[mt][nt][3] = 0.f;
        }
    // h1 writes ordered before GEMM2 reads by gemm_mma's first barrier.

    // ---- GEMM2: D2 = h1 @ W2 (sb=1: c0->buf1, c1->buf2, c2->buf0, c3->buf1) --
    gemm_mma(su, Au, Wu, g_W2h, 1, m0, n0, gid, tig, c);

    // ---- epilogue2: relu(D2 + b2), shuffle-reduce, one atomicAdd per col ----
    {
        int jl = mw >> 1, sub = mw & 1;
#pragma unroll
        for (int nt = 0; nt < 8; nt++) {
            int col = n0 + nt * 8 + 2 * tig;
            float bb0 = b2s[col], bb1 = b2s[col + 1];
            float s0 = fmaxf(c[0][nt][0] + bb0, 0.f) + fmaxf(c[0][nt][2] + bb0, 0.f) +
                       fmaxf(c[1][nt][0] + bb0, 0.f) + fmaxf(c[1][nt][2] + bb0, 0.f);
            float s1 = fmaxf(c[0][nt][1] + bb1, 0.f) + fmaxf(c[0][nt][3] + bb1, 0.f) +
                       fmaxf(c[1][nt][1] + bb1, 0.f) + fmaxf(c[1][nt][3] + bb1, 0.f);
#pragma unroll
            for (int msk = 4; msk <= 16; msk <<= 1) {
                s0 += __shfl_xor_sync(0xFFFFFFFF, s0, msk);
                s1 += __shfl_xor_sync(0xFFFFFFFF, s1, msk);
            }
            if (gid == 0) {
                red[(jl * 2 + sub) * GH + col] = s0;
                red[(jl * 2 + sub) * GH + col + 1] = s1;
            }
        }
        __syncthreads();
        if (tid < GH) {
            float t = (red[tid] + red[GH + tid]) + (red[2 * GH + tid] + red[3 * GH + tid]);
            atomicAdd(&g_emb[b * GH + tid], t);
        }
    }
}

// ---------------- K3: f MLP (reads g_emb directly) ---------------------------
__global__ __launch_bounds__(256) void f_kernel(const float* __restrict__ fw0,
                                                const float* __restrict__ fb0,
                                                const float* __restrict__ fw1,
                                                const float* __restrict__ fb1,
                                                float* __restrict__ out) {
    __shared__ float e[GH];
    __shared__ float h[GH];
    __shared__ float red[8 * FOUT];
    int b = blockIdx.x, tid = threadIdx.x;

    e[tid] = g_emb[b * GH + tid];
    __syncthreads();

    // h[n] = relu(e . fw0[:,n] + fb0[n]) (8 chains)
    {
        float a[8];
#pragma unroll
        for (int u = 0; u < 8; u++) a[u] = 0.f;
#pragma unroll 4
        for (int k = 0; k < GH; k += 8)
#pragma unroll
            for (int u = 0; u < 8; u++)
                a[u] = fmaf(e[k + u], fw0[(k + u) * GH + tid], a[u]);
        float t = ((a[0] + a[1]) + (a[2] + a[3])) + ((a[4] + a[5]) + (a[6] + a[7]));
        h[tid] = fmaxf(t + fb0[tid], 0.f);
    }
    __syncthreads();

    // out = h @ fw1 + fb1, k split across 8 warps
    {
        int w = tid >> 5, lane = tid & 31;
        float ps = 0.f;
#pragma unroll
        for (int kk = 0; kk < 32; kk++) {
            int k = w * 32 + kk;
            ps = fmaf(h[k], fw1[k * FOUT + lane], ps);
        }
        red[w * FOUT + lane] = ps;
        __syncthreads();
        if (tid < FOUT) {
            float a = fb1[tid];
#pragma unroll
            for (int t = 0; t < 8; t++) a += red[t * FOUT + tid];
            out[b * FOUT + tid] = a;
        }
    }
}

// ---------------- launch ----------------------------------------------------
extern "C" void kernel_launch(void* const* d_in, const int* in_sizes, int n_in,
                              void* d_out, int out_size) {
    const float* x   = (const float*)d_in[0];
    const float* q   = (const float*)d_in[1];
    const float* gw0 = (const float*)d_in[2];
    const float* gb0 = (const float*)d_in[3];
    const float* gw1 = (const float*)d_in[4];
    const float* gb1 = (const float*)d_in[5];
    const float* gw2 = (const float*)d_in[6];
    const float* gb2 = (const float*)d_in[7];
    const float* fw0 = (const float*)d_in[8];
    const float* fb0 = (const float*)d_in[9];
    const float* fw1 = (const float*)d_in[10];
    const float* fb1 = (const float*)d_in[11];
    float* out = (float*)d_out;

    cudaFuncSetAttribute(rn_mma_kernel, cudaFuncAttributeMaxDynamicSharedMemorySize, SMEM_TOT);
    cudaFuncSetAttribute(prep_kernel, cudaFuncAttributeMaxDynamicSharedMemorySize, PREP_SMEM);

    prep_kernel<<<384, 256, PREP_SMEM>>>(x, q, gw0, gb0, gw1, gw2);
    rn_mma_kernel<<<BATCH * NFACT / 2, 512, SMEM_TOT>>>(gb1, gb2);
    f_kernel<<<BATCH, 256>>>(fw0, fb0, fw1, fb1, out);
}